// round 12
// baseline (speedup 1.0000x reference)
#include <cuda_runtime.h>
#include <cuda_fp16.h>
#include <math.h>
#include <stdint.h>

#define S    1024
#define D    2048
#define NH   32
#define HD   64
#define FF   8192
#define NE   4
#define NV   50257
#define BLKQ 64
#define NB   16   // S / BLKQ

// ---------------- scratch (static device globals; no runtime alloc) ----------------
__device__ float  g_x  [S*D];
__device__ float  g_q  [S*D];
__device__ float  g_k  [S*D];
__device__ float  g_v  [S*D];
__device__ float  g_att[S*D];
__device__ float  g_x1 [S*D];
__device__ float  g_x2 [S*D];
__device__ float  g_moe[S*D];
__device__ float  g_t1 [(long)NE*S*FF];
__device__ float  g_t2 [(long)NE*S*FF];
__device__ __half g_x2h[S*D];
__device__ __half g_t1h[(long)NE*S*FF];
__device__ __half g_x5h[S*D];
__device__ int    g_cnt[NE];
__device__ int    g_list[NE*S];
__device__ float  g_wgt[NE*S];
__device__ float  g_var[S];
__device__ float  g_cos[S*32];
__device__ float  g_sin[S*32];

// ---------------- packed f32x2 helpers ----------------
__device__ __forceinline__ uint64_t pack2(float x) {
    uint64_t r;
    uint32_t u = __float_as_uint(x);
    asm("mov.b64 %0, {%1, %1};" : "=l"(r) : "r"(u));
    return r;
}
__device__ __forceinline__ uint64_t mk2(float lo, float hi) {
    uint64_t r;
    asm("mov.b64 %0, {%1, %2};" : "=l"(r) : "r"(__float_as_uint(lo)), "r"(__float_as_uint(hi)));
    return r;
}
__device__ __forceinline__ void fma2(uint64_t& d, uint64_t a, uint64_t b) {
    asm("fma.rn.f32x2 %0, %1, %2, %0;" : "+l"(d) : "l"(a), "l"(b));
}
__device__ __forceinline__ void unpack2(uint64_t v, float& lo, float& hi) {
    uint32_t a, b;
    asm("mov.b64 {%0, %1}, %2;" : "=r"(a), "=r"(b) : "l"(v));
    lo = __uint_as_float(a); hi = __uint_as_float(b);
}
__device__ __forceinline__ uint32_t smem_u32(const void* p) {
    uint32_t a;
    asm("{ .reg .u64 t; cvta.to.shared.u64 t, %1; cvt.u32.u64 %0, t; }" : "=r"(a) : "l"(p));
    return a;
}

// ---------------- init ----------------
__global__ void zero_kernel(float* moe) {
    long i = (long)blockIdx.x * blockDim.x + threadIdx.x;
    if (i < (long)S*D) moe[i] = 0.f;
    if (i < NE) g_cnt[i] = 0;
}

// ---------------- embedding gather (float4) ----------------
__global__ void embed_kernel(const int* __restrict__ tok, const float* __restrict__ emb,
                             float* __restrict__ x) {
    int t = blockIdx.x;
    const float4* src = (const float4*)(emb + (long)tok[t] * D);
    float4* dst = (float4*)(x + (long)t * D);
    for (int d = threadIdx.x; d < D/4; d += blockDim.x)
        dst[d] = src[d];
}

// ---------------- RoPE tables ----------------
__global__ void rope_table_kernel() {
    int idx = blockIdx.x * blockDim.x + threadIdx.x;
    if (idx >= S*32) return;
    int j = idx & 31;
    int s = idx >> 5;
    double inv = pow(10000.0, -(double)(2*j) / (double)HD);
    double ang = (double)s * inv;
    g_cos[idx] = (float)cos(ang);
    g_sin[idx] = (float)sin(ang);
}

__global__ void rope_kernel(float* __restrict__ q, float* __restrict__ k) {
    int idx = blockIdx.x * blockDim.x + threadIdx.x;
    if (idx >= S*NH*(HD/2)) return;
    int j = idx & 31;
    int h = (idx >> 5) & 31;
    int s = idx >> 10;
    float c  = g_cos[s*32 + j];
    float sn = g_sin[s*32 + j];
    long base = (long)s*D + h*HD + 2*j;
    float q0 = q[base], q1 = q[base+1];
    q[base]   = q0*c - q1*sn;
    q[base+1] = q0*sn + q1*c;
    float k0 = k[base], k1 = k[base+1];
    k[base]   = k0*c - k1*sn;
    k[base+1] = k0*sn + k1*c;
}

// ---------------- attention (per-block-max softmax; f32x2 packed, bit-exact) ---------
#define ATTN_SMEM ((64*64 + 64*64 + 64*64 + 8*64) * 4)
__global__ void attn_kernel(const float* __restrict__ q, const float* __restrict__ k,
                            const float* __restrict__ v, float* __restrict__ o) {
    int h  = blockIdx.x;
    int ib = blockIdx.y;
    extern __shared__ float sm[];
    float* Qs  = sm;
    float* Ks2 = sm + 4096;
    float* Vs2 = sm + 8192;
    float* Ps  = sm + 12288;
    int tid = threadIdx.x;
    int w = tid >> 5, l = tid & 31;

    for (int idx = tid; idx < 64*64; idx += 256) {
        int r = idx >> 6, c = idx & 63;
        Qs[r*64 + c] = q[((long)(ib*BLKQ + r))*D + h*HD + c];
    }
    uint64_t num2[8];
    float den[8];
    #pragma unroll
    for (int r = 0; r < 8; r++) { num2[r] = 0ull; den[r] = 0.f; }

    for (int jb = 0; jb <= ib; jb++) {
        __syncthreads();
        for (int idx = tid; idx < 64*64; idx += 256) {
            int r = idx >> 6, c = idx & 63;
            float kv = k[((long)(jb*BLKQ + r))*D + h*HD + c];
            float vv = v[((long)(jb*BLKQ + r))*D + h*HD + c];
            Ks2[c*64 + (r & 31)*2 + (r >> 5)] = kv;
            Vs2[r*64 + (c & 31)*2 + (c >> 5)] = vv;
        }
        __syncthreads();
        for (int r = 0; r < 8; r++) {
            int qr = w*8 + r;
            uint64_t s2 = 0ull;
            #pragma unroll 8
            for (int d = 0; d < HD; d++) {
                uint64_t q2 = pack2(Qs[qr*64 + d]);
                uint64_t kp = *(const uint64_t*)&Ks2[d*64 + l*2];
                fma2(s2, q2, kp);
            }
            float s0, s1;
            unpack2(s2, s0, s1);
            s0 *= 0.125f; s1 *= 0.125f;
            if (jb == ib) {
                if (l      > qr) s0 = -INFINITY;
                if (l + 32 > qr) s1 = -INFINITY;
            }
            float m = fmaxf(s0, s1);
            #pragma unroll
            for (int off = 16; off; off >>= 1)
                m = fmaxf(m, __shfl_xor_sync(0xffffffffu, m, off));
            float p0 = expf(s0 - m), p1 = expf(s1 - m);
            float ds = p0 + p1;
            #pragma unroll
            for (int off = 16; off; off >>= 1)
                ds += __shfl_xor_sync(0xffffffffu, ds, off);
            den[r] += ds;
            Ps[w*64 + l] = p0; Ps[w*64 + l + 32] = p1;
            __syncwarp();
            #pragma unroll 8
            for (int kk = 0; kk < 64; kk++) {
                uint64_t pk2 = pack2(Ps[w*64 + kk]);
                uint64_t vp  = *(const uint64_t*)&Vs2[kk*64 + l*2];
                fma2(num2[r], pk2, vp);
            }
            __syncwarp();
        }
    }
    for (int r = 0; r < 8; r++) {
        int qr = w*8 + r;
        float dinv = 1.0f / (den[r] + 1e-6f);
        float n0, n1;
        unpack2(num2[r], n0, n1);
        long base = ((long)(ib*BLKQ + qr))*D + h*HD;
        o[base + l]      = n0 * dinv;
        o[base + l + 32] = n1 * dinv;
    }
}

// ---------------- layernorm (optionally also emits fp16 copy) ----------------
__global__ void ln_kernel(const float* __restrict__ x, const float* __restrict__ g,
                          const float* __restrict__ b, float* __restrict__ y,
                          __half* __restrict__ yh) {
    int t = blockIdx.x;
    __shared__ float red[256];
    const float* row = x + (long)t*D;
    float s = 0.f;
    for (int d = threadIdx.x; d < D; d += 256) s += row[d];
    red[threadIdx.x] = s; __syncthreads();
    for (int o = 128; o; o >>= 1) { if (threadIdx.x < o) red[threadIdx.x] += red[threadIdx.x+o]; __syncthreads(); }
    float mu = red[0] / (float)D;
    __syncthreads();
    float vs = 0.f;
    for (int d = threadIdx.x; d < D; d += 256) { float dd = row[d]-mu; vs = fmaf(dd, dd, vs); }
    red[threadIdx.x] = vs; __syncthreads();
    for (int o = 128; o; o >>= 1) { if (threadIdx.x < o) red[threadIdx.x] += red[threadIdx.x+o]; __syncthreads(); }
    float inv = 1.0f / sqrtf(red[0]/(float)D + 1e-5f);
    for (int d = threadIdx.x; d < D; d += 256) {
        float vvv = (row[d]-mu)*inv*g[d] + b[d];
        y[(long)t*D + d] = vvv;
        if (yh) yh[(long)t*D + d] = __float2half_rn(vvv);
    }
}

// ---------------- fused tail: x5h = half(LN(LN(moe + x2))) ----------------
__global__ void tail_kernel(const float* __restrict__ moe, const float* __restrict__ x2,
                            const float* __restrict__ g2, const float* __restrict__ b2,
                            const float* __restrict__ fg, const float* __restrict__ fb,
                            __half* __restrict__ yh) {
    int t = blockIdx.x;
    __shared__ float row[D];
    __shared__ float red[256];
    int tid = threadIdx.x;
    for (int d = tid; d < D; d += 256)
        row[d] = moe[(long)t*D + d] + x2[(long)t*D + d];
    __syncthreads();
    float s = 0.f;
    for (int d = tid; d < D; d += 256) s += row[d];
    red[tid] = s; __syncthreads();
    for (int o = 128; o; o >>= 1) { if (tid < o) red[tid] += red[tid+o]; __syncthreads(); }
    float mu = red[0] / (float)D;
    __syncthreads();
    float vs = 0.f;
    for (int d = tid; d < D; d += 256) { float dd = row[d]-mu; vs = fmaf(dd, dd, vs); }
    red[tid] = vs; __syncthreads();
    for (int o = 128; o; o >>= 1) { if (tid < o) red[tid] += red[tid+o]; __syncthreads(); }
    float inv = 1.0f / sqrtf(red[0]/(float)D + 1e-5f);
    __syncthreads();
    for (int d = tid; d < D; d += 256)
        row[d] = (row[d]-mu)*inv*g2[d] + b2[d];
    __syncthreads();
    s = 0.f;
    for (int d = tid; d < D; d += 256) s += row[d];
    red[tid] = s; __syncthreads();
    for (int o = 128; o; o >>= 1) { if (tid < o) red[tid] += red[tid+o]; __syncthreads(); }
    mu = red[0] / (float)D;
    __syncthreads();
    vs = 0.f;
    for (int d = tid; d < D; d += 256) { float dd = row[d]-mu; vs = fmaf(dd, dd, vs); }
    red[tid] = vs; __syncthreads();
    for (int o = 128; o; o >>= 1) { if (tid < o) red[tid] += red[tid+o]; __syncthreads(); }
    inv = 1.0f / sqrtf(red[0]/(float)D + 1e-5f);
    for (int d = tid; d < D; d += 256)
        yh[(long)t*D + d] = __float2half_rn((row[d]-mu)*inv*fg[d] + fb[d]);
}

// ---------------- gate ----------------
__global__ void gate_kernel(const float* __restrict__ x, const float* __restrict__ gw) {
    int t = blockIdx.x;
    int tid = threadIdx.x;  // 128
    __shared__ float red[4][128];
    const float* row = x + (long)t*D;
    float p[4] = {0.f,0.f,0.f,0.f};
    for (int d = tid; d < D; d += 128) {
        float xv = row[d];
        #pragma unroll
        for (int e = 0; e < 4; e++) p[e] = fmaf(xv, gw[e*D + d], p[e]);
    }
    #pragma unroll
    for (int e = 0; e < 4; e++) red[e][tid] = p[e];
    __syncthreads();
    for (int o = 64; o; o >>= 1) {
        if (tid < o) {
            red[0][tid] += red[0][tid+o];
            red[1][tid] += red[1][tid+o];
            red[2][tid] += red[2][tid+o];
            red[3][tid] += red[3][tid+o];
        }
        __syncthreads();
    }
    if (tid == 0) {
        float l[4];
        #pragma unroll
        for (int e = 0; e < 4; e++) l[e] = red[e][0];
        float mu = (l[0]+l[1]+l[2]+l[3]) * 0.25f;
        float var = 0.f;
        #pragma unroll
        for (int e = 0; e < 4; e++) { float d0 = l[e]-mu; var = fmaf(d0, d0, var); }
        g_var[t] = var / 3.0f;
        int i1 = 0;
        for (int e = 1; e < 4; e++) if (l[e] > l[i1]) i1 = e;
        int i2 = (i1 == 0) ? 1 : 0;
        for (int e = 0; e < 4; e++) if (e != i1 && l[e] > l[i2]) i2 = e;
        float m = fmaxf(fmaxf(l[0],l[1]), fmaxf(l[2],l[3]));
        float e1 = expf(l[i1]-m), e2 = expf(l[i2]-m);
        float w1 = e1/(e1+e2), w2 = e2/(e1+e2);
        int pos1 = atomicAdd(&g_cnt[i1], 1);
        g_list[i1*S + pos1] = t; g_wgt[i1*S + pos1] = w1;
        int pos2 = atomicAdd(&g_cnt[i2], 1);
        g_list[i2*S + pos2] = t; g_wgt[i2*S + pos2] = w2;
    }
}

// ---------------- aux ----------------
__global__ void aux_kernel(float* __restrict__ out, int out_size) {
    __shared__ float red[256];
    float s = 0.f;
    for (int i = threadIdx.x; i < S; i += 256) s += g_var[i];
    red[threadIdx.x] = s; __syncthreads();
    for (int o = 128; o; o >>= 1) { if (threadIdx.x < o) red[threadIdx.x] += red[threadIdx.x+o]; __syncthreads(); }
    if (threadIdx.x == 0) {
        long pos = (long)S * NV;
        if ((long)out_size > pos) out[pos] = red[0] / (float)S;
    }
}

// ---------------- silu-gate on valid routed rows: writes fp16 directly ----------------
__global__ void silu_kernel() {
    int row = blockIdx.x;
    int e = row >> 10;
    int slot = row & (S-1);
    if (slot >= g_cnt[e]) return;
    long base = (long)row * FF;
    const float4* t1p = (const float4*)(g_t1 + base);
    const float4* t2p = (const float4*)(g_t2 + base);
    uint2* oh = (uint2*)(g_t1h + base);
    for (int i = threadIdx.x; i < FF/4; i += 256) {
        float4 a = t1p[i], b = t2p[i];
        a.x = b.x * (a.x / (1.0f + expf(-a.x)));
        a.y = b.y * (a.y / (1.0f + expf(-a.y)));
        a.z = b.z * (a.z / (1.0f + expf(-a.z)));
        a.w = b.w * (a.w / (1.0f + expf(-a.w)));
        __half2 lo = __floats2half2_rn(a.x, a.y);
        __half2 hi = __floats2half2_rn(a.z, a.w);
        uint2 pk;
        pk.x = *(uint32_t*)&lo;
        pk.y = *(uint32_t*)&hi;
        oh[i] = pk;
    }
}

// ================= fp32 SGEMM via packed f32x2, BK=16, software-pipelined =============
constexpr int BM = 128, BN = 128, BKs = 16;

template<int EPI>
__device__ __forceinline__ void sgemm_body(
    const float* __restrict__ A, const float* __restrict__ Bm, float* __restrict__ Cm,
    int M, int N, int K, int m0, int n0, const float* __restrict__ resid)
{
    __shared__ float As[BKs][BM];
    __shared__ float Bs[BKs][BN];
    int tid = threadIdx.x;
    int tx = tid & 15, ty = tid >> 4;

    uint64_t acc2[8][4];
    #pragma unroll
    for (int i = 0; i < 8; i++)
        #pragma unroll
        for (int j = 0; j < 4; j++) acc2[i][j] = 0ull;

    int lrow = tid >> 1;
    int lq   = (tid & 1) * 8;
    int arow = m0 + lrow;
    bool avld = arow < M;
    const float* Ap = avld ? (A + (long)arow * K + lq) : nullptr;
    int brow = n0 + lrow;
    bool bvld = brow < N;
    const float* Bp = bvld ? (Bm + (long)brow * K + lq) : nullptr;

    const float4 z4 = make_float4(0.f,0.f,0.f,0.f);
    float4 a0, a1, b0, b1;
    auto gload = [&](int k0) {
        a0 = avld ? *(const float4*)(Ap + k0)     : z4;
        a1 = avld ? *(const float4*)(Ap + k0 + 4) : z4;
        b0 = bvld ? *(const float4*)(Bp + k0)     : z4;
        b1 = bvld ? *(const float4*)(Bp + k0 + 4) : z4;
    };
    auto sstore = [&]() {
        As[lq+0][lrow]=a0.x; As[lq+1][lrow]=a0.y; As[lq+2][lrow]=a0.z; As[lq+3][lrow]=a0.w;
        As[lq+4][lrow]=a1.x; As[lq+5][lrow]=a1.y; As[lq+6][lrow]=a1.z; As[lq+7][lrow]=a1.w;
        Bs[lq+0][lrow]=b0.x; Bs[lq+1][lrow]=b0.y; Bs[lq+2][lrow]=b0.z; Bs[lq+3][lrow]=b0.w;
        Bs[lq+4][lrow]=b1.x; Bs[lq+5][lrow]=b1.y; Bs[lq+6][lrow]=b1.z; Bs[lq+7][lrow]=b1.w;
    };

    int T = K / BKs;
    gload(0);
    sstore();
    __syncthreads();

    for (int t = 0; t < T; t++) {
        bool more = (t + 1) < T;
        if (more) gload((t + 1) * BKs);
        #pragma unroll
        for (int kk = 0; kk < BKs; kk++) {
            float4 af0 = *(const float4*)&As[kk][ty*8];
            float4 af1 = *(const float4*)&As[kk][ty*8 + 4];
            float4 bf0 = *(const float4*)&Bs[kk][tx*8];
            float4 bf1 = *(const float4*)&Bs[kk][tx*8 + 4];
            uint64_t b2[4];
            b2[0] = mk2(bf0.x, bf0.y); b2[1] = mk2(bf0.z, bf0.w);
            b2[2] = mk2(bf1.x, bf1.y); b2[3] = mk2(bf1.z, bf1.w);
            float a[8] = {af0.x, af0.y, af0.z, af0.w, af1.x, af1.y, af1.z, af1.w};
            #pragma unroll
            for (int i = 0; i < 8; i++) {
                uint64_t a2 = pack2(a[i]);
                #pragma unroll
                for (int j = 0; j < 4; j++) fma2(acc2[i][j], a2, b2[j]);
            }
        }
        if (more) {
            __syncthreads();
            sstore();
            __syncthreads();
        }
    }
    #pragma unroll
    for (int i = 0; i < 8; i++) {
        int m = m0 + ty*8 + i;
        if (m >= M) continue;
        #pragma unroll
        for (int j = 0; j < 4; j++) {
            float c0, c1;
            unpack2(acc2[i][j], c0, c1);
            int n = n0 + tx*8 + 2*j;
            if (n < N) {
                if constexpr (EPI == 0) Cm[(long)m*N + n] = c0;
                else                    Cm[(long)m*N + n] = c0 + resid[(long)m*N + n];
            }
            if (n + 1 < N) {
                if constexpr (EPI == 0) Cm[(long)m*N + n + 1] = c1;
                else                    Cm[(long)m*N + n + 1] = c1 + resid[(long)m*N + n + 1];
            }
        }
    }
}

__global__ void __launch_bounds__(256)
wo_gemm(const float* __restrict__ A, const float* __restrict__ Bm, float* __restrict__ Cm,
        const float* __restrict__ resid) {
    sgemm_body<1>(A, Bm, Cm, S, D, D, blockIdx.y * BM, blockIdx.x * BN, resid);
}

__global__ void __launch_bounds__(256)
qkv_gemm(const float* __restrict__ x,
         const float* __restrict__ wq, const float* __restrict__ wk, const float* __restrict__ wv,
         float* __restrict__ q, float* __restrict__ k, float* __restrict__ v) {
    const float* Bm = (blockIdx.z == 0) ? wq : (blockIdx.z == 1) ? wk : wv;
    float*       Cm = (blockIdx.z == 0) ? q  : (blockIdx.z == 1) ? k  : v;
    sgemm_body<0>(x, Bm, Cm, S, D, D, blockIdx.y * BM, blockIdx.x * BN, nullptr);
}

// ================= fp16 tensor-core GEMM: 128x256 block tile, 64x64 warp tile =========
// 8 warps (2 M x 4 N), mma.m16n8k16, A fp16 gmem, B fp32->fp16 at load.
constexpr int TBM = 128, TBN = 256, THK = 32;
constexpr int KPADH = 40;
constexpr size_t TSMEM = (size_t)2 * (TBM + TBN) * KPADH * sizeof(__half);  // 61440 B

__device__ __forceinline__ void ldsm4(uint32_t& r0, uint32_t& r1, uint32_t& r2, uint32_t& r3,
                                      uint32_t addr) {
    asm volatile("ldmatrix.sync.aligned.m8n8.x4.shared.b16 {%0,%1,%2,%3}, [%4];"
                 : "=r"(r0), "=r"(r1), "=r"(r2), "=r"(r3) : "r"(addr));
}

template<int EPI, bool GA>
__device__ __forceinline__ void tgemm_body(
    const __half* __restrict__ A, const float* __restrict__ Bm, float* __restrict__ Cm,
    int Meff, int N, int K,
    const int* __restrict__ ridx, const float* __restrict__ rw,
    int m0, int n0)
{
    extern __shared__ __half hsh[];
    __half* Ah = hsh;                       // [2][TBM][KPADH]
    __half* Bh = hsh + 2*TBM*KPADH;         // [2][TBN][KPADH]
    uint32_t Abase = smem_u32(Ah);
    uint32_t Bbase = smem_u32(Bh);

    int tid = threadIdx.x, lane = tid & 31, wid = tid >> 5;
    int wm = (wid & 1) * 64;
    int wn = (wid >> 1) * 64;
    int lr = lane >> 2;
    int lc = lane & 3;

    int rr  = lane & 7, sub = lane >> 3;
    int a_row = rr + ((sub & 1) << 3);
    int a_kh  = (sub >> 1) << 3;
    int b_row = rr + ((sub >> 1) << 3);
    int b_kh  = (sub & 1) << 3;

    float acc[4][8][4];
    #pragma unroll
    for (int mt = 0; mt < 4; mt++)
        #pragma unroll
        for (int nt = 0; nt < 8; nt++)
            #pragma unroll
            for (int r = 0; r < 4; r++) acc[mt][nt][r] = 0.f;

    // A loader: fp16 128 rows, per thread 1 row x 2x16B
    int arow_l = tid >> 1;
    int ach    = (tid & 1) * 16;
    const __half* ApH;
    {
        int arow = m0 + arow_l;
        bool av = arow < Meff;
        long grow = av ? (GA ? (long)ridx[arow] : (long)arow) : 0;
        ApH = av ? (A + grow*(long)K + ach) : nullptr;
    }
    // B loader: fp32 256 rows, per thread 8 rows (stride 32) x float4 at kq
    int kq = (tid & 7) * 4;
    int r0l = tid >> 3;
    const float* Bp[8];
    #pragma unroll
    for (int i = 0; i < 8; i++) {
        int brow = n0 + r0l + 32*i;
        Bp[i] = (brow < N) ? (Bm + (long)brow*K + kq) : nullptr;
    }

    uint4 av0, av1;
    uint2 sbh[8];                 // pre-converted half2 pairs
    const uint4 zu4 = make_uint4(0,0,0,0);
    auto gload = [&](int kt) {
        av0 = ApH ? *(const uint4*)(ApH + (long)kt*THK)     : zu4;
        av1 = ApH ? *(const uint4*)(ApH + (long)kt*THK + 8) : zu4;
        #pragma unroll
        for (int i = 0; i < 8; i++) {
            float4 bb = Bp[i] ? *(const float4*)(Bp[i] + (long)kt*THK) : make_float4(0.f,0.f,0.f,0.f);
            __half2 b01 = __floats2half2_rn(bb.x, bb.y);
            __half2 b23 = __floats2half2_rn(bb.z, bb.w);
            sbh[i].x = *(uint32_t*)&b01;
            sbh[i].y = *(uint32_t*)&b23;
        }
    };
    auto sstore = [&](int buf) {
        uint4* pa = (uint4*)&Ah[((long)buf*TBM + arow_l)*KPADH + ach];
        pa[0] = av0; pa[1] = av1;
        #pragma unroll
        for (int i = 0; i < 8; i++) {
            int ar = r0l + 32*i;
            *(uint2*)&Bh[((long)buf*TBN + ar)*KPADH + kq] = sbh[i];
        }
    };

    int ktiles = K / THK;
    gload(0);
    sstore(0);
    __syncthreads();

    for (int t = 0; t < ktiles; t++) {
        int buf = t & 1;
        bool more = (t + 1) < ktiles;
        if (more) gload(t + 1);

        uint32_t Abuf = Abase + (uint32_t)buf * TBM * KPADH * 2;
        uint32_t Bbuf = Bbase + (uint32_t)buf * TBN * KPADH * 2;

        #pragma unroll
        for (int ks = 0; ks < 2; ks++) {
            int kb = ks * 16;
            uint32_t af[4][4], bf[8][2];
            #pragma unroll
            for (int mt = 0; mt < 4; mt++) {
                uint32_t addr = Abuf + (uint32_t)((wm + mt*16 + a_row) * KPADH + kb + a_kh) * 2;
                ldsm4(af[mt][0], af[mt][1], af[mt][2], af[mt][3], addr);
            }
            #pragma unroll
            for (int p = 0; p < 4; p++) {
                uint32_t addr = Bbuf + (uint32_t)((wn + p*16 + b_row) * KPADH + kb + b_kh) * 2;
                ldsm4(bf[2*p][0], bf[2*p][1], bf[2*p+1][0], bf[2*p+1][1], addr);
            }
            #pragma unroll
            for (int mt = 0; mt < 4; mt++)
                #pragma unroll
                for (int nt = 0; nt < 8; nt++) {
                    asm volatile(
                        "mma.sync.aligned.m16n8k16.row.col.f32.f16.f16.f32 "
                        "{%0,%1,%2,%3}, {%4,%5,%6,%7}, {%8,%9}, {%0,%1,%2,%3};"
                        : "+f"(acc[mt][nt][0]), "+f"(acc[mt][nt][1]),
                          "+f"(acc[mt][nt][2]), "+f"(acc[mt][nt][3])
                        : "r"(af[mt][0]), "r"(af[mt][1]), "r"(af[mt][2]), "r"(af[mt][3]),
                          "r"(bf[nt][0]), "r"(bf[nt][1]));
                }
        }

        if (more) {
            sstore(buf ^ 1);
            __syncthreads();
        }
    }

    // ---------------- epilogue ----------------
    #pragma unroll
    for (int mt = 0; mt < 4; mt++) {
        int r0 = m0 + wm + mt*16 + lr;
        int r1 = r0 + 8;
        #pragma unroll
        for (int nt = 0; nt < 8; nt++) {
            int c0 = n0 + wn + nt*8 + (lc << 1);
            int c1 = c0 + 1;
            if constexpr (EPI == 0) {
                if (r0 < Meff) {
                    if (c0 < N) Cm[(long)r0*N + c0] = acc[mt][nt][0];
                    if (c1 < N) Cm[(long)r0*N + c1] = acc[mt][nt][1];
                }
                if (r1 < Meff) {
                    if (c0 < N) Cm[(long)r1*N + c0] = acc[mt][nt][2];
                    if (c1 < N) Cm[(long)r1*N + c1] = acc[mt][nt][3];
                }
            } else {
                if (r0 < Meff) {
                    long orow = (long)ridx[r0] * N;
                    float w = rw[r0];
                    if (c0 < N) atomicAdd(&Cm[orow + c0], acc[mt][nt][0] * w);
                    if (c1 < N) atomicAdd(&Cm[orow + c1], acc[mt][nt][1] * w);
                }
                if (r1 < Meff) {
                    long orow = (long)ridx[r1] * N;
                    float w = rw[r1];
                    if (c0 < N) atomicAdd(&Cm[orow + c0], acc[mt][nt][2] * w);
                    if (c1 < N) atomicAdd(&Cm[orow + c1], acc[mt][nt][3] * w);
                }
            }
        }
    }
}

// merged w1 + w3 MoE GEMM: z in [0, 2*NE) -> (expert, which-weight)
__global__ void __launch_bounds__(256, 1)
moe13_gemm(const float* __restrict__ w1, const float* __restrict__ w3,
           float* __restrict__ t1, float* __restrict__ t2) {
    int z = blockIdx.z;
    int e = z & (NE-1);
    int sel = z >> 2;
    int Meff = g_cnt[e];
    int m0 = blockIdx.y * TBM;
    if (m0 >= Meff) return;
    const float* Bm = (sel ? w3 : w1) + (long)e * FF * D;
    float*       Cm = (sel ? t2 : t1) + (long)e * S * FF;
    tgemm_body<0, true>(g_x2h, Bm, Cm, Meff, FF, D, g_list + e*S, nullptr,
                        m0, blockIdx.x * TBN);
}

// w2 GEMM with weighted scatter epilogue: z = expert
__global__ void __launch_bounds__(256, 1)
moe2_gemm(const float* __restrict__ w2, float* __restrict__ moe) {
    int e = blockIdx.z;
    int Meff = g_cnt[e];
    int m0 = blockIdx.y * TBM;
    if (m0 >= Meff) return;
    tgemm_body<2, false>(g_t1h + (long)e*S*FF, w2 + (long)e*D*FF, moe,
                         Meff, D, FF, g_list + e*S, g_wgt + e*S,
                         m0, blockIdx.x * TBN);
}

// LM head
__global__ void __launch_bounds__(256, 1)
head_gemm(const float* __restrict__ hw, float* __restrict__ out) {
    tgemm_body<0, false>(g_x5h, hw, out, S, NV, D, nullptr, nullptr,
                         blockIdx.y * TBM, blockIdx.x * TBN);
}

// ---------------- launcher ----------------
extern "C" void kernel_launch(void* const* d_in, const int* in_sizes, int n_in,
                              void* d_out, int out_size) {
    const int*   tokens = (const int*)  d_in[0];
    const float* emb    = (const float*)d_in[1];
    const float* wq     = (const float*)d_in[2];
    const float* wk     = (const float*)d_in[3];
    const float* wv     = (const float*)d_in[4];
    const float* wo     = (const float*)d_in[5];
    const float* ln1g   = (const float*)d_in[6];
    const float* ln1b   = (const float*)d_in[7];
    const float* gatew  = (const float*)d_in[8];
    const float* w1     = (const float*)d_in[9];
    const float* w2     = (const float*)d_in[10];
    const float* w3     = (const float*)d_in[11];
    const float* ln2g   = (const float*)d_in[12];
    const float* ln2b   = (const float*)d_in[13];
    const float* fing   = (const float*)d_in[14];
    const float* finb   = (const float*)d_in[15];
    const float* headw  = (const float*)d_in[16];
    float* out = (float*)d_out;

    float *x, *q, *k, *v, *att, *x1, *x2, *moe, *t1, *t2;
    __half *x2h, *x5h;
    cudaGetSymbolAddress((void**)&x,   g_x);
    cudaGetSymbolAddress((void**)&q,   g_q);
    cudaGetSymbolAddress((void**)&k,   g_k);
    cudaGetSymbolAddress((void**)&v,   g_v);
    cudaGetSymbolAddress((void**)&att, g_att);
    cudaGetSymbolAddress((void**)&x1,  g_x1);
    cudaGetSymbolAddress((void**)&x2,  g_x2);
    cudaGetSymbolAddress((void**)&moe, g_moe);
    cudaGetSymbolAddress((void**)&t1,  g_t1);
    cudaGetSymbolAddress((void**)&t2,  g_t2);
    cudaGetSymbolAddress((void**)&x2h, g_x2h);
    cudaGetSymbolAddress((void**)&x5h, g_x5h);

    cudaFuncSetAttribute(attn_kernel, cudaFuncAttributeMaxDynamicSharedMemorySize, ATTN_SMEM);
    cudaFuncSetAttribute(moe13_gemm, cudaFuncAttributeMaxDynamicSharedMemorySize, (int)TSMEM);
    cudaFuncSetAttribute(moe2_gemm,  cudaFuncAttributeMaxDynamicSharedMemorySize, (int)TSMEM);
    cudaFuncSetAttribute(head_gemm,  cudaFuncAttributeMaxDynamicSharedMemorySize, (int)TSMEM);

    // 0. init + rope tables
    zero_kernel<<<(S*D + 255)/256, 256>>>(moe);
    rope_table_kernel<<<(S*32 + 255)/256, 256>>>();
    // 1. embedding
    embed_kernel<<<S, 256>>>(tokens, emb, x);
    // 2. QKV projections (fp32 f32x2, pipelined — routing bit-exact)
    qkv_gemm<<<dim3(D/BN, S/BM, 3), 256>>>(x, wq, wk, wv, q, k, v);
    // 3. RoPE
    rope_kernel<<<(S*NH*(HD/2))/256, 256>>>(q, k);
    // 4. attention
    attn_kernel<<<dim3(NH, NB), 256, ATTN_SMEM>>>(q, k, v, att);
    // 5. output projection + residual (fp32 f32x2, pipelined)
    wo_gemm<<<dim3(D/BN, S/BM, 1), 256>>>(att, wo, x1, x);
    // 6. layernorm 1 (emits fp32 + fp16)
    ln_kernel<<<S, 256>>>(x1, ln1g, ln1b, x2, x2h);
    // 7. gating + routing + per-token variance
    gate_kernel<<<S, 128>>>(x2, gatew);
    aux_kernel<<<1, 256>>>(out, out_size);
    // 8. MoE expert GEMMs — fp16 tensor cores, 128x256 tiles
    moe13_gemm<<<dim3(FF/TBN, S/TBM, 2*NE), 256, TSMEM>>>(w1, w3, t1, t2);
    silu_kernel<<<NE*S, 256>>>();
    moe2_gemm<<<dim3(D/TBN, S/TBM, NE), 256, TSMEM>>>(w2, moe);
    // 9. fused residual + double layernorm -> fp16 x5
    tail_kernel<<<S, 256>>>(moe, x2, ln2g, ln2b, fing, finb, x5h);
    // 10. LM head — fp16 tensor cores, 128x256 tiles
    head_gemm<<<dim3((NV + TBN - 1)/TBN, S/TBM, 1), 256, TSMEM>>>(headw, out);
}

// round 13
// speedup vs baseline: 1.1824x; 1.1824x over previous
#include <cuda_runtime.h>
#include <cuda_fp16.h>
#include <math.h>
#include <stdint.h>

#define S    1024
#define D    2048
#define NH   32
#define HD   64
#define FF   8192
#define NE   4
#define NV   50257
#define BLKQ 64
#define NB   16   // S / BLKQ

// ---------------- scratch (static device globals; no runtime alloc) ----------------
__device__ float  g_x  [S*D];
__device__ float  g_q  [S*D];
__device__ float  g_k  [S*D];
__device__ float  g_v  [S*D];
__device__ float  g_att[S*D];
__device__ float  g_x1 [S*D];
__device__ float  g_x2 [S*D];
__device__ float  g_t1 [(long)NE*S*FF];
__device__ float  g_t2 [(long)NE*S*FF];   // later reused as [NE][S][D] expert outputs
__device__ __half g_x2h[S*D];
__device__ __half g_t1h[(long)NE*S*FF];
__device__ __half g_x5h[S*D];
__device__ int    g_cnt[NE];
__device__ int    g_list[NE*S];
__device__ float  g_wgt[NE*S];
__device__ int    g_tok_e[S*2];
__device__ int    g_tok_s[S*2];
__device__ float  g_tok_w[S*2];
__device__ float  g_var[S];
__device__ float  g_cos[S*32];
__device__ float  g_sin[S*32];

// ---------------- packed f32x2 helpers ----------------
__device__ __forceinline__ uint64_t pack2(float x) {
    uint64_t r;
    uint32_t u = __float_as_uint(x);
    asm("mov.b64 %0, {%1, %1};" : "=l"(r) : "r"(u));
    return r;
}
__device__ __forceinline__ uint64_t mk2(float lo, float hi) {
    uint64_t r;
    asm("mov.b64 %0, {%1, %2};" : "=l"(r) : "r"(__float_as_uint(lo)), "r"(__float_as_uint(hi)));
    return r;
}
__device__ __forceinline__ void fma2(uint64_t& d, uint64_t a, uint64_t b) {
    asm("fma.rn.f32x2 %0, %1, %2, %0;" : "+l"(d) : "l"(a), "l"(b));
}
__device__ __forceinline__ void unpack2(uint64_t v, float& lo, float& hi) {
    uint32_t a, b;
    asm("mov.b64 {%0, %1}, %2;" : "=r"(a), "=r"(b) : "l"(v));
    lo = __uint_as_float(a); hi = __uint_as_float(b);
}
__device__ __forceinline__ uint32_t smem_u32(const void* p) {
    uint32_t a;
    asm("{ .reg .u64 t; cvta.to.shared.u64 t, %1; cvt.u32.u64 %0, t; }" : "=r"(a) : "l"(p));
    return a;
}

// ---------------- init ----------------
__global__ void zero_kernel() {
    int i = threadIdx.x;
    if (i < NE) g_cnt[i] = 0;
}

// ---------------- embedding gather (float4) ----------------
__global__ void embed_kernel(const int* __restrict__ tok, const float* __restrict__ emb,
                             float* __restrict__ x) {
    int t = blockIdx.x;
    const float4* src = (const float4*)(emb + (long)tok[t] * D);
    float4* dst = (float4*)(x + (long)t * D);
    for (int d = threadIdx.x; d < D/4; d += blockDim.x)
        dst[d] = src[d];
}

// ---------------- RoPE tables ----------------
__global__ void rope_table_kernel() {
    int idx = blockIdx.x * blockDim.x + threadIdx.x;
    if (idx >= S*32) return;
    int j = idx & 31;
    int s = idx >> 5;
    double inv = pow(10000.0, -(double)(2*j) / (double)HD);
    double ang = (double)s * inv;
    g_cos[idx] = (float)cos(ang);
    g_sin[idx] = (float)sin(ang);
}

__global__ void rope_kernel(float* __restrict__ q, float* __restrict__ k) {
    int idx = blockIdx.x * blockDim.x + threadIdx.x;
    if (idx >= S*NH*(HD/2)) return;
    int j = idx & 31;
    int h = (idx >> 5) & 31;
    int s = idx >> 10;
    float c  = g_cos[s*32 + j];
    float sn = g_sin[s*32 + j];
    long base = (long)s*D + h*HD + 2*j;
    float q0 = q[base], q1 = q[base+1];
    q[base]   = q0*c - q1*sn;
    q[base+1] = q0*sn + q1*c;
    float k0 = k[base], k1 = k[base+1];
    k[base]   = k0*c - k1*sn;
    k[base+1] = k0*sn + k1*c;
}

// ---------------- attention (per-block-max softmax; f32x2 packed, bit-exact) ---------
#define ATTN_SMEM ((64*64 + 64*64 + 64*64 + 8*64) * 4)
__global__ void attn_kernel(const float* __restrict__ q, const float* __restrict__ k,
                            const float* __restrict__ v, float* __restrict__ o) {
    int h  = blockIdx.x;
    int ib = blockIdx.y;
    extern __shared__ float sm[];
    float* Qs  = sm;
    float* Ks2 = sm + 4096;
    float* Vs2 = sm + 8192;
    float* Ps  = sm + 12288;
    int tid = threadIdx.x;
    int w = tid >> 5, l = tid & 31;

    for (int idx = tid; idx < 64*64; idx += 256) {
        int r = idx >> 6, c = idx & 63;
        Qs[r*64 + c] = q[((long)(ib*BLKQ + r))*D + h*HD + c];
    }
    uint64_t num2[8];
    float den[8];
    #pragma unroll
    for (int r = 0; r < 8; r++) { num2[r] = 0ull; den[r] = 0.f; }

    for (int jb = 0; jb <= ib; jb++) {
        __syncthreads();
        for (int idx = tid; idx < 64*64; idx += 256) {
            int r = idx >> 6, c = idx & 63;
            float kv = k[((long)(jb*BLKQ + r))*D + h*HD + c];
            float vv = v[((long)(jb*BLKQ + r))*D + h*HD + c];
            Ks2[c*64 + (r & 31)*2 + (r >> 5)] = kv;
            Vs2[r*64 + (c & 31)*2 + (c >> 5)] = vv;
        }
        __syncthreads();
        for (int r = 0; r < 8; r++) {
            int qr = w*8 + r;
            uint64_t s2 = 0ull;
            #pragma unroll 8
            for (int d = 0; d < HD; d++) {
                uint64_t q2 = pack2(Qs[qr*64 + d]);
                uint64_t kp = *(const uint64_t*)&Ks2[d*64 + l*2];
                fma2(s2, q2, kp);
            }
            float s0, s1;
            unpack2(s2, s0, s1);
            s0 *= 0.125f; s1 *= 0.125f;
            if (jb == ib) {
                if (l      > qr) s0 = -INFINITY;
                if (l + 32 > qr) s1 = -INFINITY;
            }
            float m = fmaxf(s0, s1);
            #pragma unroll
            for (int off = 16; off; off >>= 1)
                m = fmaxf(m, __shfl_xor_sync(0xffffffffu, m, off));
            float p0 = expf(s0 - m), p1 = expf(s1 - m);
            float ds = p0 + p1;
            #pragma unroll
            for (int off = 16; off; off >>= 1)
                ds += __shfl_xor_sync(0xffffffffu, ds, off);
            den[r] += ds;
            Ps[w*64 + l] = p0; Ps[w*64 + l + 32] = p1;
            __syncwarp();
            #pragma unroll 8
            for (int kk = 0; kk < 64; kk++) {
                uint64_t pk2 = pack2(Ps[w*64 + kk]);
                uint64_t vp  = *(const uint64_t*)&Vs2[kk*64 + l*2];
                fma2(num2[r], pk2, vp);
            }
            __syncwarp();
        }
    }
    for (int r = 0; r < 8; r++) {
        int qr = w*8 + r;
        float dinv = 1.0f / (den[r] + 1e-6f);
        float n0, n1;
        unpack2(num2[r], n0, n1);
        long base = ((long)(ib*BLKQ + qr))*D + h*HD;
        o[base + l]      = n0 * dinv;
        o[base + l + 32] = n1 * dinv;
    }
}

// ---------------- layernorm (optionally also emits fp16 copy) ----------------
__global__ void ln_kernel(const float* __restrict__ x, const float* __restrict__ g,
                          const float* __restrict__ b, float* __restrict__ y,
                          __half* __restrict__ yh) {
    int t = blockIdx.x;
    __shared__ float red[256];
    const float* row = x + (long)t*D;
    float s = 0.f;
    for (int d = threadIdx.x; d < D; d += 256) s += row[d];
    red[threadIdx.x] = s; __syncthreads();
    for (int o = 128; o; o >>= 1) { if (threadIdx.x < o) red[threadIdx.x] += red[threadIdx.x+o]; __syncthreads(); }
    float mu = red[0] / (float)D;
    __syncthreads();
    float vs = 0.f;
    for (int d = threadIdx.x; d < D; d += 256) { float dd = row[d]-mu; vs = fmaf(dd, dd, vs); }
    red[threadIdx.x] = vs; __syncthreads();
    for (int o = 128; o; o >>= 1) { if (threadIdx.x < o) red[threadIdx.x] += red[threadIdx.x+o]; __syncthreads(); }
    float inv = 1.0f / sqrtf(red[0]/(float)D + 1e-5f);
    for (int d = threadIdx.x; d < D; d += 256) {
        float vvv = (row[d]-mu)*inv*g[d] + b[d];
        y[(long)t*D + d] = vvv;
        if (yh) yh[(long)t*D + d] = __float2half_rn(vvv);
    }
}

// --------- fused tail: gather expert outputs + residual + double LN -> fp16 ----------
__global__ void tail_kernel(const float* __restrict__ x2,
                            const float* __restrict__ g2, const float* __restrict__ b2,
                            const float* __restrict__ fg, const float* __restrict__ fb,
                            __half* __restrict__ yh) {
    int t = blockIdx.x;
    __shared__ float row[D];
    __shared__ float red[256];
    int tid = threadIdx.x;
    int  e1 = g_tok_e[t*2],   e2 = g_tok_e[t*2+1];
    int  s1 = g_tok_s[t*2],   s2 = g_tok_s[t*2+1];
    float w1 = g_tok_w[t*2],  w2 = g_tok_w[t*2+1];
    const float* y1 = g_t2 + ((long)e1*S + s1) * D;
    const float* y2 = g_t2 + ((long)e2*S + s2) * D;
    // moe combine (bit-matches old atomic path: round(w1*y1) + round(w2*y2)) + resid
    for (int d = tid; d < D; d += 256) {
        float a = w1 * y1[d];
        float b = w2 * y2[d];
        row[d] = (a + b) + x2[(long)t*D + d];
    }
    __syncthreads();
    float s = 0.f;
    for (int d = tid; d < D; d += 256) s += row[d];
    red[tid] = s; __syncthreads();
    for (int o = 128; o; o >>= 1) { if (tid < o) red[tid] += red[tid+o]; __syncthreads(); }
    float mu = red[0] / (float)D;
    __syncthreads();
    float vs = 0.f;
    for (int d = tid; d < D; d += 256) { float dd = row[d]-mu; vs = fmaf(dd, dd, vs); }
    red[tid] = vs; __syncthreads();
    for (int o = 128; o; o >>= 1) { if (tid < o) red[tid] += red[tid+o]; __syncthreads(); }
    float inv = 1.0f / sqrtf(red[0]/(float)D + 1e-5f);
    __syncthreads();
    for (int d = tid; d < D; d += 256)
        row[d] = (row[d]-mu)*inv*g2[d] + b2[d];
    __syncthreads();
    s = 0.f;
    for (int d = tid; d < D; d += 256) s += row[d];
    red[tid] = s; __syncthreads();
    for (int o = 128; o; o >>= 1) { if (tid < o) red[tid] += red[tid+o]; __syncthreads(); }
    mu = red[0] / (float)D;
    __syncthreads();
    vs = 0.f;
    for (int d = tid; d < D; d += 256) { float dd = row[d]-mu; vs = fmaf(dd, dd, vs); }
    red[tid] = vs; __syncthreads();
    for (int o = 128; o; o >>= 1) { if (tid < o) red[tid] += red[tid+o]; __syncthreads(); }
    inv = 1.0f / sqrtf(red[0]/(float)D + 1e-5f);
    for (int d = tid; d < D; d += 256)
        yh[(long)t*D + d] = __float2half_rn((row[d]-mu)*inv*fg[d] + fb[d]);
}

// ---------------- gate (+ per-token inverse routing map) ----------------
__global__ void gate_kernel(const float* __restrict__ x, const float* __restrict__ gw) {
    int t = blockIdx.x;
    int tid = threadIdx.x;  // 128
    __shared__ float red[4][128];
    const float* row = x + (long)t*D;
    float p[4] = {0.f,0.f,0.f,0.f};
    for (int d = tid; d < D; d += 128) {
        float xv = row[d];
        #pragma unroll
        for (int e = 0; e < 4; e++) p[e] = fmaf(xv, gw[e*D + d], p[e]);
    }
    #pragma unroll
    for (int e = 0; e < 4; e++) red[e][tid] = p[e];
    __syncthreads();
    for (int o = 64; o; o >>= 1) {
        if (tid < o) {
            red[0][tid] += red[0][tid+o];
            red[1][tid] += red[1][tid+o];
            red[2][tid] += red[2][tid+o];
            red[3][tid] += red[3][tid+o];
        }
        __syncthreads();
    }
    if (tid == 0) {
        float l[4];
        #pragma unroll
        for (int e = 0; e < 4; e++) l[e] = red[e][0];
        float mu = (l[0]+l[1]+l[2]+l[3]) * 0.25f;
        float var = 0.f;
        #pragma unroll
        for (int e = 0; e < 4; e++) { float d0 = l[e]-mu; var = fmaf(d0, d0, var); }
        g_var[t] = var / 3.0f;
        int i1 = 0;
        for (int e = 1; e < 4; e++) if (l[e] > l[i1]) i1 = e;
        int i2 = (i1 == 0) ? 1 : 0;
        for (int e = 0; e < 4; e++) if (e != i1 && l[e] > l[i2]) i2 = e;
        float m = fmaxf(fmaxf(l[0],l[1]), fmaxf(l[2],l[3]));
        float e1 = expf(l[i1]-m), e2 = expf(l[i2]-m);
        float w1 = e1/(e1+e2), w2 = e2/(e1+e2);
        int pos1 = atomicAdd(&g_cnt[i1], 1);
        g_list[i1*S + pos1] = t; g_wgt[i1*S + pos1] = w1;
        int pos2 = atomicAdd(&g_cnt[i2], 1);
        g_list[i2*S + pos2] = t; g_wgt[i2*S + pos2] = w2;
        g_tok_e[t*2] = i1;   g_tok_s[t*2] = pos1;   g_tok_w[t*2] = w1;
        g_tok_e[t*2+1] = i2; g_tok_s[t*2+1] = pos2; g_tok_w[t*2+1] = w2;
    }
}

// ---------------- aux ----------------
__global__ void aux_kernel(float* __restrict__ out, int out_size) {
    __shared__ float red[256];
    float s = 0.f;
    for (int i = threadIdx.x; i < S; i += 256) s += g_var[i];
    red[threadIdx.x] = s; __syncthreads();
    for (int o = 128; o; o >>= 1) { if (threadIdx.x < o) red[threadIdx.x] += red[threadIdx.x+o]; __syncthreads(); }
    if (threadIdx.x == 0) {
        long pos = (long)S * NV;
        if ((long)out_size > pos) out[pos] = red[0] / (float)S;
    }
}

// ---------------- silu-gate on valid routed rows: writes fp16 directly ----------------
__global__ void silu_kernel() {
    int row = blockIdx.x;
    int e = row >> 10;
    int slot = row & (S-1);
    if (slot >= g_cnt[e]) return;
    long base = (long)row * FF;
    const float4* t1p = (const float4*)(g_t1 + base);
    const float4* t2p = (const float4*)(g_t2 + base);
    uint2* oh = (uint2*)(g_t1h + base);
    for (int i = threadIdx.x; i < FF/4; i += 256) {
        float4 a = t1p[i], b = t2p[i];
        a.x = b.x * (a.x / (1.0f + expf(-a.x)));
        a.y = b.y * (a.y / (1.0f + expf(-a.y)));
        a.z = b.z * (a.z / (1.0f + expf(-a.z)));
        a.w = b.w * (a.w / (1.0f + expf(-a.w)));
        __half2 lo = __floats2half2_rn(a.x, a.y);
        __half2 hi = __floats2half2_rn(a.z, a.w);
        uint2 pk;
        pk.x = *(uint32_t*)&lo;
        pk.y = *(uint32_t*)&hi;
        oh[i] = pk;
    }
}

// ================= fp32 SGEMM via packed f32x2, BK=16, software-pipelined =============
constexpr int BM = 128, BN = 128, BKs = 16;

template<int EPI>
__device__ __forceinline__ void sgemm_body(
    const float* __restrict__ A, const float* __restrict__ Bm, float* __restrict__ Cm,
    int M, int N, int K, int m0, int n0, const float* __restrict__ resid)
{
    __shared__ float As[BKs][BM];
    __shared__ float Bs[BKs][BN];
    int tid = threadIdx.x;
    int tx = tid & 15, ty = tid >> 4;

    uint64_t acc2[8][4];
    #pragma unroll
    for (int i = 0; i < 8; i++)
        #pragma unroll
        for (int j = 0; j < 4; j++) acc2[i][j] = 0ull;

    int lrow = tid >> 1;
    int lq   = (tid & 1) * 8;
    int arow = m0 + lrow;
    bool avld = arow < M;
    const float* Ap = avld ? (A + (long)arow * K + lq) : nullptr;
    int brow = n0 + lrow;
    bool bvld = brow < N;
    const float* Bp = bvld ? (Bm + (long)brow * K + lq) : nullptr;

    const float4 z4 = make_float4(0.f,0.f,0.f,0.f);
    float4 a0, a1, b0, b1;
    auto gload = [&](int k0) {
        a0 = avld ? *(const float4*)(Ap + k0)     : z4;
        a1 = avld ? *(const float4*)(Ap + k0 + 4) : z4;
        b0 = bvld ? *(const float4*)(Bp + k0)     : z4;
        b1 = bvld ? *(const float4*)(Bp + k0 + 4) : z4;
    };
    auto sstore = [&]() {
        As[lq+0][lrow]=a0.x; As[lq+1][lrow]=a0.y; As[lq+2][lrow]=a0.z; As[lq+3][lrow]=a0.w;
        As[lq+4][lrow]=a1.x; As[lq+5][lrow]=a1.y; As[lq+6][lrow]=a1.z; As[lq+7][lrow]=a1.w;
        Bs[lq+0][lrow]=b0.x; Bs[lq+1][lrow]=b0.y; Bs[lq+2][lrow]=b0.z; Bs[lq+3][lrow]=b0.w;
        Bs[lq+4][lrow]=b1.x; Bs[lq+5][lrow]=b1.y; Bs[lq+6][lrow]=b1.z; Bs[lq+7][lrow]=b1.w;
    };

    int T = K / BKs;
    gload(0);
    sstore();
    __syncthreads();

    for (int t = 0; t < T; t++) {
        bool more = (t + 1) < T;
        if (more) gload((t + 1) * BKs);
        #pragma unroll
        for (int kk = 0; kk < BKs; kk++) {
            float4 af0 = *(const float4*)&As[kk][ty*8];
            float4 af1 = *(const float4*)&As[kk][ty*8 + 4];
            float4 bf0 = *(const float4*)&Bs[kk][tx*8];
            float4 bf1 = *(const float4*)&Bs[kk][tx*8 + 4];
            uint64_t b2[4];
            b2[0] = mk2(bf0.x, bf0.y); b2[1] = mk2(bf0.z, bf0.w);
            b2[2] = mk2(bf1.x, bf1.y); b2[3] = mk2(bf1.z, bf1.w);
            float a[8] = {af0.x, af0.y, af0.z, af0.w, af1.x, af1.y, af1.z, af1.w};
            #pragma unroll
            for (int i = 0; i < 8; i++) {
                uint64_t a2 = pack2(a[i]);
                #pragma unroll
                for (int j = 0; j < 4; j++) fma2(acc2[i][j], a2, b2[j]);
            }
        }
        if (more) {
            __syncthreads();
            sstore();
            __syncthreads();
        }
    }
    #pragma unroll
    for (int i = 0; i < 8; i++) {
        int m = m0 + ty*8 + i;
        if (m >= M) continue;
        #pragma unroll
        for (int j = 0; j < 4; j++) {
            float c0, c1;
            unpack2(acc2[i][j], c0, c1);
            int n = n0 + tx*8 + 2*j;
            if (n < N) {
                if constexpr (EPI == 0) Cm[(long)m*N + n] = c0;
                else                    Cm[(long)m*N + n] = c0 + resid[(long)m*N + n];
            }
            if (n + 1 < N) {
                if constexpr (EPI == 0) Cm[(long)m*N + n + 1] = c1;
                else                    Cm[(long)m*N + n + 1] = c1 + resid[(long)m*N + n + 1];
            }
        }
    }
}

__global__ void __launch_bounds__(256)
wo_gemm(const float* __restrict__ A, const float* __restrict__ Bm, float* __restrict__ Cm,
        const float* __restrict__ resid) {
    sgemm_body<1>(A, Bm, Cm, S, D, D, blockIdx.y * BM, blockIdx.x * BN, resid);
}

__global__ void __launch_bounds__(256)
qkv_gemm(const float* __restrict__ x,
         const float* __restrict__ wq, const float* __restrict__ wk, const float* __restrict__ wv,
         float* __restrict__ q, float* __restrict__ k, float* __restrict__ v) {
    const float* Bm = (blockIdx.z == 0) ? wq : (blockIdx.z == 1) ? wk : wv;
    float*       Cm = (blockIdx.z == 0) ? q  : (blockIdx.z == 1) ? k  : v;
    sgemm_body<0>(x, Bm, Cm, S, D, D, blockIdx.y * BM, blockIdx.x * BN, nullptr);
}

// ================= fp16 tensor-core GEMM (R11 config): 128x128, 64x32 warp tile ======
constexpr int TBM = 128, TBN = 128, THK = 32;
constexpr int KPADH = 40;
constexpr size_t TSMEM = (size_t)2 * 2 * TBM * KPADH * sizeof(__half);  // 40960 B

__device__ __forceinline__ void ldsm4(uint32_t& r0, uint32_t& r1, uint32_t& r2, uint32_t& r3,
                                      uint32_t addr) {
    asm volatile("ldmatrix.sync.aligned.m8n8.x4.shared.b16 {%0,%1,%2,%3}, [%4];"
                 : "=r"(r0), "=r"(r1), "=r"(r2), "=r"(r3) : "r"(addr));
}

template<bool GA>
__device__ __forceinline__ void tgemm_body(
    const __half* __restrict__ A, const float* __restrict__ Bm, float* __restrict__ Cm,
    int Meff, int N, int K,
    const int* __restrict__ ridx,
    int m0, int n0)
{
    extern __shared__ __half hsh[];
    __half* Ah = hsh;                       // [2][TBM][KPADH]
    __half* Bh = hsh + 2*TBM*KPADH;
    uint32_t Abase = smem_u32(Ah);
    uint32_t Bbase = smem_u32(Bh);

    int tid = threadIdx.x, lane = tid & 31, wid = tid >> 5;
    int wm = (wid & 1) * 64;
    int wn = (wid >> 1) * 32;
    int lr = lane >> 2;
    int lc = lane & 3;

    int rr  = lane & 7, sub = lane >> 3;
    int a_row = rr + ((sub & 1) << 3);
    int a_kh  = (sub >> 1) << 3;
    int b_row = rr + ((sub >> 1) << 3);
    int b_kh  = (sub & 1) << 3;

    float acc[4][4][4];
    #pragma unroll
    for (int mt = 0; mt < 4; mt++)
        #pragma unroll
        for (int nt = 0; nt < 4; nt++)
            #pragma unroll
            for (int r = 0; r < 4; r++) acc[mt][nt][r] = 0.f;

    // A loader: fp16 rows, per thread one row, 2x16B chunk
    int arow_l = tid >> 1;
    int ach    = (tid & 1) * 16;
    const __half* ApH;
    {
        int arow = m0 + arow_l;
        bool av = arow < Meff;
        long grow = av ? (GA ? (long)ridx[arow] : (long)arow) : 0;
        ApH = av ? (A + grow*(long)K + ach) : nullptr;
    }
    // B loader: fp32 rows, 4 rows per thread, float4 at kq
    int kq = (tid & 7) * 4;
    int r0l = tid >> 3;
    const float* Bp[4];
    #pragma unroll
    for (int i = 0; i < 4; i++) {
        int brow = n0 + r0l + 32*i;
        Bp[i] = (brow < N) ? (Bm + (long)brow*K + kq) : nullptr;
    }

    uint4 av0, av1;
    float4 sb[4];
    const float4 z4 = make_float4(0.f,0.f,0.f,0.f);
    const uint4 zu4 = make_uint4(0,0,0,0);
    auto gload = [&](int kt) {
        av0 = ApH ? *(const uint4*)(ApH + (long)kt*THK)     : zu4;
        av1 = ApH ? *(const uint4*)(ApH + (long)kt*THK + 8) : zu4;
        #pragma unroll
        for (int i = 0; i < 4; i++)
            sb[i] = Bp[i] ? *(const float4*)(Bp[i] + (long)kt*THK) : z4;
    };
    auto sstore = [&](int buf) {
        uint4* pa = (uint4*)&Ah[((long)buf*TBM + arow_l)*KPADH + ach];
        pa[0] = av0; pa[1] = av1;
        #pragma unroll
        for (int i = 0; i < 4; i++) {
            int ar = r0l + 32*i;
            __half2 b01 = __floats2half2_rn(sb[i].x, sb[i].y);
            __half2 b23 = __floats2half2_rn(sb[i].z, sb[i].w);
            __half2* pb = (__half2*)&Bh[((long)buf*TBM + ar)*KPADH + kq];
            pb[0] = b01; pb[1] = b23;
        }
    };

    int ktiles = K / THK;
    gload(0);
    sstore(0);
    __syncthreads();

    for (int t = 0; t < ktiles; t++) {
        int buf = t & 1;
        bool more = (t + 1) < ktiles;
        if (more) gload(t + 1);

        uint32_t Abuf = Abase + (uint32_t)buf * TBM * KPADH * 2;
        uint32_t Bbuf = Bbase + (uint32_t)buf * TBM * KPADH * 2;

        #pragma unroll
        for (int ks = 0; ks < 2; ks++) {
            int kb = ks * 16;
            uint32_t af[4][4], bf[4][2];
            #pragma unroll
            for (int mt = 0; mt < 4; mt++) {
                uint32_t addr = Abuf + (uint32_t)((wm + mt*16 + a_row) * KPADH + kb + a_kh) * 2;
                ldsm4(af[mt][0], af[mt][1], af[mt][2], af[mt][3], addr);
            }
            #pragma unroll
            for (int p = 0; p < 2; p++) {
                uint32_t addr = Bbuf + (uint32_t)((wn + p*16 + b_row) * KPADH + kb + b_kh) * 2;
                ldsm4(bf[2*p][0], bf[2*p][1], bf[2*p+1][0], bf[2*p+1][1], addr);
            }
            #pragma unroll
            for (int mt = 0; mt < 4; mt++)
                #pragma unroll
                for (int nt = 0; nt < 4; nt++) {
                    asm volatile(
                        "mma.sync.aligned.m16n8k16.row.col.f32.f16.f16.f32 "
                        "{%0,%1,%2,%3}, {%4,%5,%6,%7}, {%8,%9}, {%0,%1,%2,%3};"
                        : "+f"(acc[mt][nt][0]), "+f"(acc[mt][nt][1]),
                          "+f"(acc[mt][nt][2]), "+f"(acc[mt][nt][3])
                        : "r"(af[mt][0]), "r"(af[mt][1]), "r"(af[mt][2]), "r"(af[mt][3]),
                          "r"(bf[nt][0]), "r"(bf[nt][1]));
                }
        }

        if (more) {
            sstore(buf ^ 1);
            __syncthreads();
        }
    }

    // ---------------- epilogue: plain stores ----------------
    #pragma unroll
    for (int mt = 0; mt < 4; mt++) {
        int r0 = m0 + wm + mt*16 + lr;
        int r1 = r0 + 8;
        #pragma unroll
        for (int nt = 0; nt < 4; nt++) {
            int c0 = n0 + wn + nt*8 + (lc << 1);
            int c1 = c0 + 1;
            if (r0 < Meff) {
                if (c0 < N) Cm[(long)r0*N + c0] = acc[mt][nt][0];
                if (c1 < N) Cm[(long)r0*N + c1] = acc[mt][nt][1];
            }
            if (r1 < Meff) {
                if (c0 < N) Cm[(long)r1*N + c0] = acc[mt][nt][2];
                if (c1 < N) Cm[(long)r1*N + c1] = acc[mt][nt][3];
            }
        }
    }
}

// merged w1 + w3 MoE GEMM: z in [0, 2*NE) -> (expert, which-weight)
__global__ void __launch_bounds__(256, 2)
moe13_gemm(const float* __restrict__ w1, const float* __restrict__ w3,
           float* __restrict__ t1, float* __restrict__ t2) {
    int z = blockIdx.z;
    int e = z & (NE-1);
    int sel = z >> 2;
    int Meff = g_cnt[e];
    int m0 = blockIdx.y * TBM;
    if (m0 >= Meff) return;
    const float* Bm = (sel ? w3 : w1) + (long)e * FF * D;
    float*       Cm = (sel ? t2 : t1) + (long)e * S * FF;
    tgemm_body<true>(g_x2h, Bm, Cm, Meff, FF, D, g_list + e*S, m0, blockIdx.x * TBN);
}

// w2 GEMM: compact per-expert output rows (no atomics)
__global__ void __launch_bounds__(256, 2)
moe2_gemm(const float* __restrict__ w2, float* __restrict__ yout) {
    int e = blockIdx.z;
    int Meff = g_cnt[e];
    int m0 = blockIdx.y * TBM;
    if (m0 >= Meff) return;
    tgemm_body<false>(g_t1h + (long)e*S*FF, w2 + (long)e*D*FF, yout + (long)e*S*D,
                      Meff, D, FF, nullptr, m0, blockIdx.x * TBN);
}

// LM head
__global__ void __launch_bounds__(256, 2)
head_gemm(const float* __restrict__ hw, float* __restrict__ out) {
    tgemm_body<false>(g_x5h, hw, out, S, NV, D, nullptr, blockIdx.y * TBM, blockIdx.x * TBN);
}

// ---------------- launcher ----------------
extern "C" void kernel_launch(void* const* d_in, const int* in_sizes, int n_in,
                              void* d_out, int out_size) {
    const int*   tokens = (const int*)  d_in[0];
    const float* emb    = (const float*)d_in[1];
    const float* wq     = (const float*)d_in[2];
    const float* wk     = (const float*)d_in[3];
    const float* wv     = (const float*)d_in[4];
    const float* wo     = (const float*)d_in[5];
    const float* ln1g   = (const float*)d_in[6];
    const float* ln1b   = (const float*)d_in[7];
    const float* gatew  = (const float*)d_in[8];
    const float* w1     = (const float*)d_in[9];
    const float* w2     = (const float*)d_in[10];
    const float* w3     = (const float*)d_in[11];
    const float* ln2g   = (const float*)d_in[12];
    const float* ln2b   = (const float*)d_in[13];
    const float* fing   = (const float*)d_in[14];
    const float* finb   = (const float*)d_in[15];
    const float* headw  = (const float*)d_in[16];
    float* out = (float*)d_out;

    float *x, *q, *k, *v, *att, *x1, *x2, *t1, *t2;
    __half *x2h, *x5h;
    cudaGetSymbolAddress((void**)&x,   g_x);
    cudaGetSymbolAddress((void**)&q,   g_q);
    cudaGetSymbolAddress((void**)&k,   g_k);
    cudaGetSymbolAddress((void**)&v,   g_v);
    cudaGetSymbolAddress((void**)&att, g_att);
    cudaGetSymbolAddress((void**)&x1,  g_x1);
    cudaGetSymbolAddress((void**)&x2,  g_x2);
    cudaGetSymbolAddress((void**)&t1,  g_t1);
    cudaGetSymbolAddress((void**)&t2,  g_t2);
    cudaGetSymbolAddress((void**)&x2h, g_x2h);
    cudaGetSymbolAddress((void**)&x5h, g_x5h);

    cudaFuncSetAttribute(attn_kernel, cudaFuncAttributeMaxDynamicSharedMemorySize, ATTN_SMEM);

    // 0. init + rope tables
    zero_kernel<<<1, 32>>>();
    rope_table_kernel<<<(S*32 + 255)/256, 256>>>();
    // 1. embedding
    embed_kernel<<<S, 256>>>(tokens, emb, x);
    // 2. QKV projections (fp32 f32x2, pipelined — routing bit-exact)
    qkv_gemm<<<dim3(D/BN, S/BM, 3), 256>>>(x, wq, wk, wv, q, k, v);
    // 3. RoPE
    rope_kernel<<<(S*NH*(HD/2))/256, 256>>>(q, k);
    // 4. attention
    attn_kernel<<<dim3(NH, NB), 256, ATTN_SMEM>>>(q, k, v, att);
    // 5. output projection + residual (fp32 f32x2, pipelined)
    wo_gemm<<<dim3(D/BN, S/BM, 1), 256>>>(att, wo, x1, x);
    // 6. layernorm 1 (emits fp32 + fp16)
    ln_kernel<<<S, 256>>>(x1, ln1g, ln1b, x2, x2h);
    // 7. gating + routing + per-token variance
    gate_kernel<<<S, 128>>>(x2, gatew);
    aux_kernel<<<1, 256>>>(out, out_size);
    // 8. MoE expert GEMMs — fp16 tensor cores, fp16 A operands
    moe13_gemm<<<dim3(FF/TBN, S/TBM, 2*NE), 256, TSMEM>>>(w1, w3, t1, t2);
    silu_kernel<<<NE*S, 256>>>();
    moe2_gemm<<<dim3(D/TBN, S/TBM, NE), 256, TSMEM>>>(w2, t2);   // t2 reused: [NE][S][D]
    // 9. fused gather + residual + double layernorm -> fp16 x5
    tail_kernel<<<S, 256>>>(x2, ln2g, ln2b, fing, finb, x5h);
    // 10. LM head — fp16 tensor cores, fp16 A
    head_gemm<<<dim3((NV + TBN - 1)/TBN, S/TBM, 1), 256, TSMEM>>>(headw, out);
}

// round 14
// speedup vs baseline: 1.2537x; 1.0603x over previous
#include <cuda_runtime.h>
#include <cuda_fp16.h>
#include <math.h>
#include <stdint.h>

#define S    1024
#define D    2048
#define NH   32
#define HD   64
#define FF   8192
#define NE   4
#define NV   50257
#define BLKQ 64
#define NB   16   // S / BLKQ

// ---------------- scratch (static device globals; no runtime alloc) ----------------
__device__ float  g_x  [S*D];
__device__ float  g_q  [S*D];
__device__ float  g_k  [S*D];
__device__ float  g_v  [S*D];
__device__ float  g_x1 [S*D];
__device__ float  g_x2 [S*D];
__device__ float  g_t1 [(long)NE*S*FF];
__device__ float  g_t2 [(long)NE*S*FF];   // later reused as [NE][S][D] expert outputs
__device__ __half g_x2h[S*D];
__device__ __half g_t1h[(long)NE*S*FF];
__device__ __half g_x5h[S*D];
__device__ __half g_xsp  [(long)S*4*D];        // x split [hi,lo,hi,lo]
__device__ __half g_attsp[(long)S*4*D];        // attention out split
__device__ __half g_wsp  [(long)3*D*4*D];      // wq/wk/wv split [whi,whi,wlo,wlo]
__device__ __half g_wosp [(long)D*4*D];        // wo split
__device__ int    g_cnt[NE];
__device__ int    g_list[NE*S];
__device__ float  g_wgt[NE*S];
__device__ int    g_tok_e[S*2];
__device__ int    g_tok_s[S*2];
__device__ float  g_tok_w[S*2];
__device__ float  g_var[S];
__device__ float  g_cos[S*32];
__device__ float  g_sin[S*32];

// ---------------- packed f32x2 helpers ----------------
__device__ __forceinline__ uint64_t pack2(float x) {
    uint64_t r;
    uint32_t u = __float_as_uint(x);
    asm("mov.b64 %0, {%1, %1};" : "=l"(r) : "r"(u));
    return r;
}
__device__ __forceinline__ void fma2(uint64_t& d, uint64_t a, uint64_t b) {
    asm("fma.rn.f32x2 %0, %1, %2, %0;" : "+l"(d) : "l"(a), "l"(b));
}
__device__ __forceinline__ void unpack2(uint64_t v, float& lo, float& hi) {
    uint32_t a, b;
    asm("mov.b64 {%0, %1}, %2;" : "=r"(a), "=r"(b) : "l"(v));
    lo = __uint_as_float(a); hi = __uint_as_float(b);
}
__device__ __forceinline__ uint32_t smem_u32(const void* p) {
    uint32_t a;
    asm("{ .reg .u64 t; cvta.to.shared.u64 t, %1; cvt.u32.u64 %0, t; }" : "=r"(a) : "l"(p));
    return a;
}

// ---------------- init ----------------
__global__ void zero_kernel() {
    int i = threadIdx.x;
    if (i < NE) g_cnt[i] = 0;
}

// ---------------- embedding gather (float4) ----------------
__global__ void embed_kernel(const int* __restrict__ tok, const float* __restrict__ emb,
                             float* __restrict__ x) {
    int t = blockIdx.x;
    const float4* src = (const float4*)(emb + (long)tok[t] * D);
    float4* dst = (float4*)(x + (long)t * D);
    for (int d = threadIdx.x; d < D/4; d += blockDim.x)
        dst[d] = src[d];
}

// ---------------- split builders ----------------
// A-pattern: [hi, lo, hi, lo];  B-pattern: [whi, whi, wlo, wlo]
__global__ void xsplit_kernel(const float* __restrict__ x, __half* __restrict__ sp) {
    int t = blockIdx.x;
    const float* s = x + (long)t*D;
    __half* d0 = sp + (long)t*4*D;
    for (int c = threadIdx.x; c < D; c += 256) {
        float w = s[c];
        __half hi = __float2half_rn(w);
        __half lo = __float2half_rn(w - __half2float(hi));
        d0[c] = hi; d0[D + c] = lo; d0[2*D + c] = hi; d0[3*D + c] = lo;
    }
}
__global__ void wsplit_kernel(const float* __restrict__ wq, const float* __restrict__ wk,
                              const float* __restrict__ wv, const float* __restrict__ wo) {
    int z = blockIdx.z;
    const float* src = (z == 0) ? wq : (z == 1) ? wk : (z == 2) ? wv : wo;
    __half* dst = (z < 3) ? (g_wsp + (long)z*D*4*D) : g_wosp;
    int row = blockIdx.x;
    const float* s = src + (long)row*D;
    __half* d0 = dst + (long)row*4*D;
    for (int c = threadIdx.x; c < D; c += 256) {
        float w = s[c];
        __half hi = __float2half_rn(w);
        __half lo = __float2half_rn(w - __half2float(hi));
        d0[c] = hi; d0[D + c] = hi; d0[2*D + c] = lo; d0[3*D + c] = lo;
    }
}

// ---------------- RoPE tables ----------------
__global__ void rope_table_kernel() {
    int idx = blockIdx.x * blockDim.x + threadIdx.x;
    if (idx >= S*32) return;
    int j = idx & 31;
    int s = idx >> 5;
    double inv = pow(10000.0, -(double)(2*j) / (double)HD);
    double ang = (double)s * inv;
    g_cos[idx] = (float)cos(ang);
    g_sin[idx] = (float)sin(ang);
}

__global__ void rope_kernel(float* __restrict__ q, float* __restrict__ k) {
    int idx = blockIdx.x * blockDim.x + threadIdx.x;
    if (idx >= S*NH*(HD/2)) return;
    int j = idx & 31;
    int h = (idx >> 5) & 31;
    int s = idx >> 10;
    float c  = g_cos[s*32 + j];
    float sn = g_sin[s*32 + j];
    long base = (long)s*D + h*HD + 2*j;
    float q0 = q[base], q1 = q[base+1];
    q[base]   = q0*c - q1*sn;
    q[base+1] = q0*sn + q1*c;
    float k0 = k[base], k1 = k[base+1];
    k[base]   = k0*c - k1*sn;
    k[base+1] = k0*sn + k1*c;
}

// ---------------- attention: outputs split fp16 directly ----------------
#define ATTN_SMEM ((64*64 + 64*64 + 64*64 + 8*64) * 4)
__global__ void attn_kernel(const float* __restrict__ q, const float* __restrict__ k,
                            const float* __restrict__ v, __half* __restrict__ osp) {
    int h  = blockIdx.x;
    int ib = blockIdx.y;
    extern __shared__ float sm[];
    float* Qs  = sm;
    float* Ks2 = sm + 4096;
    float* Vs2 = sm + 8192;
    float* Ps  = sm + 12288;
    int tid = threadIdx.x;
    int w = tid >> 5, l = tid & 31;

    for (int idx = tid; idx < 64*64; idx += 256) {
        int r = idx >> 6, c = idx & 63;
        Qs[r*64 + c] = q[((long)(ib*BLKQ + r))*D + h*HD + c];
    }
    uint64_t num2[8];
    float den[8];
    #pragma unroll
    for (int r = 0; r < 8; r++) { num2[r] = 0ull; den[r] = 0.f; }

    for (int jb = 0; jb <= ib; jb++) {
        __syncthreads();
        for (int idx = tid; idx < 64*64; idx += 256) {
            int r = idx >> 6, c = idx & 63;
            float kv = k[((long)(jb*BLKQ + r))*D + h*HD + c];
            float vv = v[((long)(jb*BLKQ + r))*D + h*HD + c];
            Ks2[c*64 + (r & 31)*2 + (r >> 5)] = kv;
            Vs2[r*64 + (c & 31)*2 + (c >> 5)] = vv;
        }
        __syncthreads();
        for (int r = 0; r < 8; r++) {
            int qr = w*8 + r;
            uint64_t s2 = 0ull;
            #pragma unroll 8
            for (int d = 0; d < HD; d++) {
                uint64_t q2 = pack2(Qs[qr*64 + d]);
                uint64_t kp = *(const uint64_t*)&Ks2[d*64 + l*2];
                fma2(s2, q2, kp);
            }
            float s0, s1;
            unpack2(s2, s0, s1);
            s0 *= 0.125f; s1 *= 0.125f;
            if (jb == ib) {
                if (l      > qr) s0 = -INFINITY;
                if (l + 32 > qr) s1 = -INFINITY;
            }
            float m = fmaxf(s0, s1);
            #pragma unroll
            for (int off = 16; off; off >>= 1)
                m = fmaxf(m, __shfl_xor_sync(0xffffffffu, m, off));
            float p0 = expf(s0 - m), p1 = expf(s1 - m);
            float ds = p0 + p1;
            #pragma unroll
            for (int off = 16; off; off >>= 1)
                ds += __shfl_xor_sync(0xffffffffu, ds, off);
            den[r] += ds;
            Ps[w*64 + l] = p0; Ps[w*64 + l + 32] = p1;
            __syncwarp();
            #pragma unroll 8
            for (int kk = 0; kk < 64; kk++) {
                uint64_t pk2 = pack2(Ps[w*64 + kk]);
                uint64_t vp  = *(const uint64_t*)&Vs2[kk*64 + l*2];
                fma2(num2[r], pk2, vp);
            }
            __syncwarp();
        }
    }
    for (int r = 0; r < 8; r++) {
        int qr = w*8 + r;
        float dinv = 1.0f / (den[r] + 1e-6f);
        float n0, n1;
        unpack2(num2[r], n0, n1);
        long rb = ((long)(ib*BLKQ + qr))*4*D + h*HD;
        float v0 = n0 * dinv;
        __half h0 = __float2half_rn(v0);
        __half l0 = __float2half_rn(v0 - __half2float(h0));
        osp[rb + l]       = h0; osp[rb + D + l]   = l0;
        osp[rb + 2*D + l] = h0; osp[rb + 3*D + l] = l0;
        float v1 = n1 * dinv;
        __half h1 = __float2half_rn(v1);
        __half l1 = __float2half_rn(v1 - __half2float(h1));
        osp[rb + l + 32]       = h1; osp[rb + D + l + 32]   = l1;
        osp[rb + 2*D + l + 32] = h1; osp[rb + 3*D + l + 32] = l1;
    }
}

// ---------------- layernorm (also emits fp16 copy) ----------------
__global__ void ln_kernel(const float* __restrict__ x, const float* __restrict__ g,
                          const float* __restrict__ b, float* __restrict__ y,
                          __half* __restrict__ yh) {
    int t = blockIdx.x;
    __shared__ float red[256];
    const float* row = x + (long)t*D;
    float s = 0.f;
    for (int d = threadIdx.x; d < D; d += 256) s += row[d];
    red[threadIdx.x] = s; __syncthreads();
    for (int o = 128; o; o >>= 1) { if (threadIdx.x < o) red[threadIdx.x] += red[threadIdx.x+o]; __syncthreads(); }
    float mu = red[0] / (float)D;
    __syncthreads();
    float vs = 0.f;
    for (int d = threadIdx.x; d < D; d += 256) { float dd = row[d]-mu; vs = fmaf(dd, dd, vs); }
    red[threadIdx.x] = vs; __syncthreads();
    for (int o = 128; o; o >>= 1) { if (threadIdx.x < o) red[threadIdx.x] += red[threadIdx.x+o]; __syncthreads(); }
    float inv = 1.0f / sqrtf(red[0]/(float)D + 1e-5f);
    for (int d = threadIdx.x; d < D; d += 256) {
        float vvv = (row[d]-mu)*inv*g[d] + b[d];
        y[(long)t*D + d] = vvv;
        if (yh) yh[(long)t*D + d] = __float2half_rn(vvv);
    }
}

// --------- fused tail: gather expert outputs + residual + double LN -> fp16 ----------
__global__ void tail_kernel(const float* __restrict__ x2,
                            const float* __restrict__ g2, const float* __restrict__ b2,
                            const float* __restrict__ fg, const float* __restrict__ fb,
                            __half* __restrict__ yh) {
    int t = blockIdx.x;
    __shared__ float row[D];
    __shared__ float red[256];
    int tid = threadIdx.x;
    int  e1 = g_tok_e[t*2],   e2 = g_tok_e[t*2+1];
    int  s1 = g_tok_s[t*2],   s2 = g_tok_s[t*2+1];
    float w1 = g_tok_w[t*2],  w2 = g_tok_w[t*2+1];
    const float* y1 = g_t2 + ((long)e1*S + s1) * D;
    const float* y2 = g_t2 + ((long)e2*S + s2) * D;
    for (int d = tid; d < D; d += 256) {
        float a = w1 * y1[d];
        float b = w2 * y2[d];
        row[d] = (a + b) + x2[(long)t*D + d];
    }
    __syncthreads();
    float s = 0.f;
    for (int d = tid; d < D; d += 256) s += row[d];
    red[tid] = s; __syncthreads();
    for (int o = 128; o; o >>= 1) { if (tid < o) red[tid] += red[tid+o]; __syncthreads(); }
    float mu = red[0] / (float)D;
    __syncthreads();
    float vs = 0.f;
    for (int d = tid; d < D; d += 256) { float dd = row[d]-mu; vs = fmaf(dd, dd, vs); }
    red[tid] = vs; __syncthreads();
    for (int o = 128; o; o >>= 1) { if (tid < o) red[tid] += red[tid+o]; __syncthreads(); }
    float inv = 1.0f / sqrtf(red[0]/(float)D + 1e-5f);
    __syncthreads();
    for (int d = tid; d < D; d += 256)
        row[d] = (row[d]-mu)*inv*g2[d] + b2[d];
    __syncthreads();
    s = 0.f;
    for (int d = tid; d < D; d += 256) s += row[d];
    red[tid] = s; __syncthreads();
    for (int o = 128; o; o >>= 1) { if (tid < o) red[tid] += red[tid+o]; __syncthreads(); }
    mu = red[0] / (float)D;
    __syncthreads();
    vs = 0.f;
    for (int d = tid; d < D; d += 256) { float dd = row[d]-mu; vs = fmaf(dd, dd, vs); }
    red[tid] = vs; __syncthreads();
    for (int o = 128; o; o >>= 1) { if (tid < o) red[tid] += red[tid+o]; __syncthreads(); }
    inv = 1.0f / sqrtf(red[0]/(float)D + 1e-5f);
    for (int d = tid; d < D; d += 256)
        yh[(long)t*D + d] = __float2half_rn((row[d]-mu)*inv*fg[d] + fb[d]);
}

// ---------------- gate (+ per-token inverse routing map) ----------------
__global__ void gate_kernel(const float* __restrict__ x, const float* __restrict__ gw) {
    int t = blockIdx.x;
    int tid = threadIdx.x;  // 128
    __shared__ float red[4][128];
    const float* row = x + (long)t*D;
    float p[4] = {0.f,0.f,0.f,0.f};
    for (int d = tid; d < D; d += 128) {
        float xv = row[d];
        #pragma unroll
        for (int e = 0; e < 4; e++) p[e] = fmaf(xv, gw[e*D + d], p[e]);
    }
    #pragma unroll
    for (int e = 0; e < 4; e++) red[e][tid] = p[e];
    __syncthreads();
    for (int o = 64; o; o >>= 1) {
        if (tid < o) {
            red[0][tid] += red[0][tid+o];
            red[1][tid] += red[1][tid+o];
            red[2][tid] += red[2][tid+o];
            red[3][tid] += red[3][tid+o];
        }
        __syncthreads();
    }
    if (tid == 0) {
        float l[4];
        #pragma unroll
        for (int e = 0; e < 4; e++) l[e] = red[e][0];
        float mu = (l[0]+l[1]+l[2]+l[3]) * 0.25f;
        float var = 0.f;
        #pragma unroll
        for (int e = 0; e < 4; e++) { float d0 = l[e]-mu; var = fmaf(d0, d0, var); }
        g_var[t] = var / 3.0f;
        int i1 = 0;
        for (int e = 1; e < 4; e++) if (l[e] > l[i1]) i1 = e;
        int i2 = (i1 == 0) ? 1 : 0;
        for (int e = 0; e < 4; e++) if (e != i1 && l[e] > l[i2]) i2 = e;
        float m = fmaxf(fmaxf(l[0],l[1]), fmaxf(l[2],l[3]));
        float e1 = expf(l[i1]-m), e2 = expf(l[i2]-m);
        float w1 = e1/(e1+e2), w2 = e2/(e1+e2);
        int pos1 = atomicAdd(&g_cnt[i1], 1);
        g_list[i1*S + pos1] = t; g_wgt[i1*S + pos1] = w1;
        int pos2 = atomicAdd(&g_cnt[i2], 1);
        g_list[i2*S + pos2] = t; g_wgt[i2*S + pos2] = w2;
        g_tok_e[t*2] = i1;   g_tok_s[t*2] = pos1;   g_tok_w[t*2] = w1;
        g_tok_e[t*2+1] = i2; g_tok_s[t*2+1] = pos2; g_tok_w[t*2+1] = w2;
    }
}

// ---------------- aux ----------------
__global__ void aux_kernel(float* __restrict__ out, int out_size) {
    __shared__ float red[256];
    float s = 0.f;
    for (int i = threadIdx.x; i < S; i += 256) s += g_var[i];
    red[threadIdx.x] = s; __syncthreads();
    for (int o = 128; o; o >>= 1) { if (threadIdx.x < o) red[threadIdx.x] += red[threadIdx.x+o]; __syncthreads(); }
    if (threadIdx.x == 0) {
        long pos = (long)S * NV;
        if ((long)out_size > pos) out[pos] = red[0] / (float)S;
    }
}

// ---------------- silu-gate on valid routed rows: writes fp16 directly ----------------
__global__ void silu_kernel() {
    int row = blockIdx.x;
    int e = row >> 10;
    int slot = row & (S-1);
    if (slot >= g_cnt[e]) return;
    long base = (long)row * FF;
    const float4* t1p = (const float4*)(g_t1 + base);
    const float4* t2p = (const float4*)(g_t2 + base);
    uint2* oh = (uint2*)(g_t1h + base);
    for (int i = threadIdx.x; i < FF/4; i += 256) {
        float4 a = t1p[i], b = t2p[i];
        a.x = b.x * (a.x / (1.0f + expf(-a.x)));
        a.y = b.y * (a.y / (1.0f + expf(-a.y)));
        a.z = b.z * (a.z / (1.0f + expf(-a.z)));
        a.w = b.w * (a.w / (1.0f + expf(-a.w)));
        __half2 lo = __floats2half2_rn(a.x, a.y);
        __half2 hi = __floats2half2_rn(a.z, a.w);
        uint2 pk;
        pk.x = *(uint32_t*)&lo;
        pk.y = *(uint32_t*)&hi;
        oh[i] = pk;
    }
}

// ================= fp16 tensor-core GEMM: 128x128, 64x32 warp tile ===================
// A fp16 gmem; B either fp16 gmem (BHALF) or fp32 gmem converted at load.
constexpr int TBM = 128, TBN = 128, THK = 32;
constexpr int KPADH = 40;
constexpr size_t TSMEM = (size_t)2 * 2 * TBM * KPADH * sizeof(__half);  // 40960 B

__device__ __forceinline__ void ldsm4(uint32_t& r0, uint32_t& r1, uint32_t& r2, uint32_t& r3,
                                      uint32_t addr) {
    asm volatile("ldmatrix.sync.aligned.m8n8.x4.shared.b16 {%0,%1,%2,%3}, [%4];"
                 : "=r"(r0), "=r"(r1), "=r"(r2), "=r"(r3) : "r"(addr));
}

template<int EPI, bool GA, bool BHALF>
__device__ __forceinline__ void tgemm_body(
    const __half* __restrict__ A, const void* __restrict__ Bv, float* __restrict__ Cm,
    const float* __restrict__ resid,
    int Meff, int N, int K, const int* __restrict__ ridx, int m0, int n0)
{
    extern __shared__ __half hsh[];
    __half* Ah = hsh;                       // [2][TBM][KPADH]
    __half* Bh = hsh + 2*TBM*KPADH;
    uint32_t Abase = smem_u32(Ah);
    uint32_t Bbase = smem_u32(Bh);

    int tid = threadIdx.x, lane = tid & 31, wid = tid >> 5;
    int wm = (wid & 1) * 64;
    int wn = (wid >> 1) * 32;
    int lr = lane >> 2;
    int lc = lane & 3;

    int rr  = lane & 7, sub = lane >> 3;
    int a_row = rr + ((sub & 1) << 3);
    int a_kh  = (sub >> 1) << 3;
    int b_row = rr + ((sub >> 1) << 3);
    int b_kh  = (sub & 1) << 3;

    float acc[4][4][4];
    #pragma unroll
    for (int mt = 0; mt < 4; mt++)
        #pragma unroll
        for (int nt = 0; nt < 4; nt++)
            #pragma unroll
            for (int r = 0; r < 4; r++) acc[mt][nt][r] = 0.f;

    // A loader: per thread one row, 2x16B chunk
    int arow_l = tid >> 1;
    int ach    = (tid & 1) * 16;
    const __half* ApH;
    {
        int arow = m0 + arow_l;
        bool av = arow < Meff;
        long grow = av ? (GA ? (long)ridx[arow] : (long)arow) : 0;
        ApH = av ? (A + grow*(long)K + ach) : nullptr;
    }
    // B loader
    const __half* BpH = nullptr;
    const float*  Bp[4];
    int kq = (tid & 7) * 4;
    int r0l = tid >> 3;
    if constexpr (BHALF) {
        const __half* Bg = (const __half*)Bv;
        int brow = n0 + arow_l;
        BpH = (brow < N) ? (Bg + (long)brow*K + ach) : nullptr;
    } else {
        const float* Bg = (const float*)Bv;
        #pragma unroll
        for (int i = 0; i < 4; i++) {
            int brow = n0 + r0l + 32*i;
            Bp[i] = (brow < N) ? (Bg + (long)brow*K + kq) : nullptr;
        }
    }

    uint4 av0, av1, bv0, bv1;
    float4 sb[4];
    const float4 z4 = make_float4(0.f,0.f,0.f,0.f);
    const uint4 zu4 = make_uint4(0,0,0,0);
    auto gload = [&](int kt) {
        av0 = ApH ? *(const uint4*)(ApH + (long)kt*THK)     : zu4;
        av1 = ApH ? *(const uint4*)(ApH + (long)kt*THK + 8) : zu4;
        if constexpr (BHALF) {
            bv0 = BpH ? *(const uint4*)(BpH + (long)kt*THK)     : zu4;
            bv1 = BpH ? *(const uint4*)(BpH + (long)kt*THK + 8) : zu4;
        } else {
            #pragma unroll
            for (int i = 0; i < 4; i++)
                sb[i] = Bp[i] ? *(const float4*)(Bp[i] + (long)kt*THK) : z4;
        }
    };
    auto sstore = [&](int buf) {
        uint4* pa = (uint4*)&Ah[((long)buf*TBM + arow_l)*KPADH + ach];
        pa[0] = av0; pa[1] = av1;
        if constexpr (BHALF) {
            uint4* pb = (uint4*)&Bh[((long)buf*TBM + arow_l)*KPADH + ach];
            pb[0] = bv0; pb[1] = bv1;
        } else {
            #pragma unroll
            for (int i = 0; i < 4; i++) {
                int ar = r0l + 32*i;
                __half2 b01 = __floats2half2_rn(sb[i].x, sb[i].y);
                __half2 b23 = __floats2half2_rn(sb[i].z, sb[i].w);
                __half2* pb = (__half2*)&Bh[((long)buf*TBM + ar)*KPADH + kq];
                pb[0] = b01; pb[1] = b23;
            }
        }
    };

    int ktiles = K / THK;
    gload(0);
    sstore(0);
    __syncthreads();

    for (int t = 0; t < ktiles; t++) {
        int buf = t & 1;
        bool more = (t + 1) < ktiles;
        if (more) gload(t + 1);

        uint32_t Abuf = Abase + (uint32_t)buf * TBM * KPADH * 2;
        uint32_t Bbuf = Bbase + (uint32_t)buf * TBM * KPADH * 2;

        #pragma unroll
        for (int ks = 0; ks < 2; ks++) {
            int kb = ks * 16;
            uint32_t af[4][4], bf[4][2];
            #pragma unroll
            for (int mt = 0; mt < 4; mt++) {
                uint32_t addr = Abuf + (uint32_t)((wm + mt*16 + a_row) * KPADH + kb + a_kh) * 2;
                ldsm4(af[mt][0], af[mt][1], af[mt][2], af[mt][3], addr);
            }
            #pragma unroll
            for (int p = 0; p < 2; p++) {
                uint32_t addr = Bbuf + (uint32_t)((wn + p*16 + b_row) * KPADH + kb + b_kh) * 2;
                ldsm4(bf[2*p][0], bf[2*p][1], bf[2*p+1][0], bf[2*p+1][1], addr);
            }
            #pragma unroll
            for (int mt = 0; mt < 4; mt++)
                #pragma unroll
                for (int nt = 0; nt < 4; nt++) {
                    asm volatile(
                        "mma.sync.aligned.m16n8k16.row.col.f32.f16.f16.f32 "
                        "{%0,%1,%2,%3}, {%4,%5,%6,%7}, {%8,%9}, {%0,%1,%2,%3};"
                        : "+f"(acc[mt][nt][0]), "+f"(acc[mt][nt][1]),
                          "+f"(acc[mt][nt][2]), "+f"(acc[mt][nt][3])
                        : "r"(af[mt][0]), "r"(af[mt][1]), "r"(af[mt][2]), "r"(af[mt][3]),
                          "r"(bf[nt][0]), "r"(bf[nt][1]));
                }
        }

        if (more) {
            sstore(buf ^ 1);
            __syncthreads();
        }
    }

    // ---------------- epilogue ----------------
    #pragma unroll
    for (int mt = 0; mt < 4; mt++) {
        int r0 = m0 + wm + mt*16 + lr;
        int r1 = r0 + 8;
        #pragma unroll
        for (int nt = 0; nt < 4; nt++) {
            int c0 = n0 + wn + nt*8 + (lc << 1);
            int c1 = c0 + 1;
            if (r0 < Meff) {
                if (c0 < N) {
                    float vv = acc[mt][nt][0];
                    if constexpr (EPI == 1) vv += resid[(long)r0*N + c0];
                    Cm[(long)r0*N + c0] = vv;
                }
                if (c1 < N) {
                    float vv = acc[mt][nt][1];
                    if constexpr (EPI == 1) vv += resid[(long)r0*N + c1];
                    Cm[(long)r0*N + c1] = vv;
                }
            }
            if (r1 < Meff) {
                if (c0 < N) {
                    float vv = acc[mt][nt][2];
                    if constexpr (EPI == 1) vv += resid[(long)r1*N + c0];
                    Cm[(long)r1*N + c0] = vv;
                }
                if (c1 < N) {
                    float vv = acc[mt][nt][3];
                    if constexpr (EPI == 1) vv += resid[(long)r1*N + c1];
                    Cm[(long)r1*N + c1] = vv;
                }
            }
        }
    }
}

// QKV: split-fp16 exact GEMM, z batches {q,k,v}, K' = 4D
__global__ void __launch_bounds__(256, 2)
qkv_gemm(float* __restrict__ q, float* __restrict__ k, float* __restrict__ v) {
    int z = blockIdx.z;
    float* Cm = (z == 0) ? q : (z == 1) ? k : v;
    const __half* Bm = g_wsp + (long)z*D*4*D;
    tgemm_body<0, false, true>(g_xsp, Bm, Cm, nullptr, S, D, 4*D, nullptr,
                               blockIdx.y * TBM, blockIdx.x * TBN);
}

// WO: split-fp16 exact GEMM + residual
__global__ void __launch_bounds__(256, 2)
wo_gemm(float* __restrict__ x1, const float* __restrict__ resid) {
    tgemm_body<1, false, true>(g_attsp, g_wosp, x1, resid, S, D, 4*D, nullptr,
                               blockIdx.y * TBM, blockIdx.x * TBN);
}

// merged w1 + w3 MoE GEMM: z in [0, 2*NE) -> (expert, which-weight)
__global__ void __launch_bounds__(256, 2)
moe13_gemm(const float* __restrict__ w1, const float* __restrict__ w3,
           float* __restrict__ t1, float* __restrict__ t2) {
    int z = blockIdx.z;
    int e = z & (NE-1);
    int sel = z >> 2;
    int Meff = g_cnt[e];
    int m0 = blockIdx.y * TBM;
    if (m0 >= Meff) return;
    const float* Bm = (sel ? w3 : w1) + (long)e * FF * D;
    float*       Cm = (sel ? t2 : t1) + (long)e * S * FF;
    tgemm_body<0, true, false>(g_x2h, Bm, Cm, nullptr, Meff, FF, D, g_list + e*S,
                               m0, blockIdx.x * TBN);
}

// w2 GEMM: compact per-expert output rows (no atomics)
__global__ void __launch_bounds__(256, 2)
moe2_gemm(const float* __restrict__ w2, float* __restrict__ yout) {
    int e = blockIdx.z;
    int Meff = g_cnt[e];
    int m0 = blockIdx.y * TBM;
    if (m0 >= Meff) return;
    tgemm_body<0, false, false>(g_t1h + (long)e*S*FF, w2 + (long)e*D*FF, yout + (long)e*S*D,
                                nullptr, Meff, D, FF, nullptr, m0, blockIdx.x * TBN);
}

// LM head
__global__ void __launch_bounds__(256, 2)
head_gemm(const float* __restrict__ hw, float* __restrict__ out) {
    tgemm_body<0, false, false>(g_x5h, hw, out, nullptr, S, NV, D, nullptr,
                                blockIdx.y * TBM, blockIdx.x * TBN);
}

// ---------------- launcher ----------------
extern "C" void kernel_launch(void* const* d_in, const int* in_sizes, int n_in,
                              void* d_out, int out_size) {
    const int*   tokens = (const int*)  d_in[0];
    const float* emb    = (const float*)d_in[1];
    const float* wq     = (const float*)d_in[2];
    const float* wk     = (const float*)d_in[3];
    const float* wv     = (const float*)d_in[4];
    const float* wo     = (const float*)d_in[5];
    const float* ln1g   = (const float*)d_in[6];
    const float* ln1b   = (const float*)d_in[7];
    const float* gatew  = (const float*)d_in[8];
    const float* w1     = (const float*)d_in[9];
    const float* w2     = (const float*)d_in[10];
    const float* w3     = (const float*)d_in[11];
    const float* ln2g   = (const float*)d_in[12];
    const float* ln2b   = (const float*)d_in[13];
    const float* fing   = (const float*)d_in[14];
    const float* finb   = (const float*)d_in[15];
    const float* headw  = (const float*)d_in[16];
    float* out = (float*)d_out;

    float *x, *q, *k, *v, *x1, *x2, *t1, *t2;
    __half *x2h, *x5h, *xsp, *attsp;
    cudaGetSymbolAddress((void**)&x,   g_x);
    cudaGetSymbolAddress((void**)&q,   g_q);
    cudaGetSymbolAddress((void**)&k,   g_k);
    cudaGetSymbolAddress((void**)&v,   g_v);
    cudaGetSymbolAddress((void**)&x1,  g_x1);
    cudaGetSymbolAddress((void**)&x2,  g_x2);
    cudaGetSymbolAddress((void**)&t1,  g_t1);
    cudaGetSymbolAddress((void**)&t2,  g_t2);
    cudaGetSymbolAddress((void**)&x2h, g_x2h);
    cudaGetSymbolAddress((void**)&x5h, g_x5h);
    cudaGetSymbolAddress((void**)&xsp, g_xsp);
    cudaGetSymbolAddress((void**)&attsp, g_attsp);

    cudaFuncSetAttribute(attn_kernel, cudaFuncAttributeMaxDynamicSharedMemorySize, ATTN_SMEM);

    // 0. init + rope tables + weight splits
    zero_kernel<<<1, 32>>>();
    rope_table_kernel<<<(S*32 + 255)/256, 256>>>();
    wsplit_kernel<<<dim3(D, 1, 4), 256>>>(wq, wk, wv, wo);
    // 1. embedding + x split
    embed_kernel<<<S, 256>>>(tokens, emb, x);
    xsplit_kernel<<<S, 256>>>(x, xsp);
    // 2. QKV projections — split-fp16 exact tensor-core GEMM
    qkv_gemm<<<dim3(D/TBN, S/TBM, 3), 256, TSMEM>>>(q, k, v);
    // 3. RoPE
    rope_kernel<<<(S*NH*(HD/2))/256, 256>>>(q, k);
    // 4. attention (emits split output)
    attn_kernel<<<dim3(NH, NB), 256, ATTN_SMEM>>>(q, k, v, attsp);
    // 5. output projection + residual — split-fp16 exact
    wo_gemm<<<dim3(D/TBN, S/TBM, 1), 256, TSMEM>>>(x1, x);
    // 6. layernorm 1 (emits fp32 + fp16)
    ln_kernel<<<S, 256>>>(x1, ln1g, ln1b, x2, x2h);
    // 7. gating + routing + per-token variance
    gate_kernel<<<S, 128>>>(x2, gatew);
    aux_kernel<<<1, 256>>>(out, out_size);
    // 8. MoE expert GEMMs — fp16 tensor cores
    moe13_gemm<<<dim3(FF/TBN, S/TBM, 2*NE), 256, TSMEM>>>(w1, w3, t1, t2);
    silu_kernel<<<NE*S, 256>>>();
    moe2_gemm<<<dim3(D/TBN, S/TBM, NE), 256, TSMEM>>>(w2, t2);   // t2 reused: [NE][S][D]
    // 9. fused gather + residual + double layernorm -> fp16 x5
    tail_kernel<<<S, 256>>>(x2, ln2g, ln2b, fing, finb, x5h);
    // 10. LM head — fp16 tensor cores
    head_gemm<<<dim3((NV + TBN - 1)/TBN, S/TBM, 1), 256, TSMEM>>>(headw, out);
}

// round 15
// speedup vs baseline: 1.3390x; 1.0680x over previous
#include <cuda_runtime.h>
#include <cuda_fp16.h>
#include <math.h>
#include <stdint.h>

#define S    1024
#define D    2048
#define NH   32
#define HD   64
#define FF   8192
#define NE   4
#define NV   50257
#define BLKQ 64
#define NB   16   // S / BLKQ
#define SPK  (3*D) // split-GEMM K' (hi*whi + lo*whi + hi*wlo; lo*wlo dropped)

// ---------------- scratch (static device globals; no runtime alloc) ----------------
__device__ float  g_x  [S*D];
__device__ float  g_q  [S*D];
__device__ float  g_k  [S*D];
__device__ float  g_v  [S*D];
__device__ float  g_x1 [S*D];
__device__ float  g_x2 [S*D];
__device__ float  g_t1 [(long)NE*S*FF];
__device__ float  g_t2 [(long)NE*S*FF];   // later reused as [NE][S][D] expert outputs
__device__ __half g_x2h[S*D];
__device__ __half g_t1h[(long)NE*S*FF];
__device__ __half g_x5h[S*D];
__device__ __half g_xsp  [(long)S*SPK];        // x split [hi,lo,hi]
__device__ __half g_attsp[(long)S*SPK];        // attention out split
__device__ __half g_wsp  [(long)3*D*SPK];      // wq/wk/wv split [whi,whi,wlo]
__device__ __half g_wosp [(long)D*SPK];        // wo split
__device__ int    g_cnt[NE];
__device__ int    g_list[NE*S];
__device__ float  g_wgt[NE*S];
__device__ int    g_tok_e[S*2];
__device__ int    g_tok_s[S*2];
__device__ float  g_tok_w[S*2];
__device__ float  g_var[S];
__device__ float  g_cos[S*32];
__device__ float  g_sin[S*32];

// ---------------- packed f32x2 helpers ----------------
__device__ __forceinline__ uint64_t pack2(float x) {
    uint64_t r;
    uint32_t u = __float_as_uint(x);
    asm("mov.b64 %0, {%1, %1};" : "=l"(r) : "r"(u));
    return r;
}
__device__ __forceinline__ void fma2(uint64_t& d, uint64_t a, uint64_t b) {
    asm("fma.rn.f32x2 %0, %1, %2, %0;" : "+l"(d) : "l"(a), "l"(b));
}
__device__ __forceinline__ void unpack2(uint64_t v, float& lo, float& hi) {
    uint32_t a, b;
    asm("mov.b64 {%0, %1}, %2;" : "=r"(a), "=r"(b) : "l"(v));
    lo = __uint_as_float(a); hi = __uint_as_float(b);
}
__device__ __forceinline__ uint32_t smem_u32(const void* p) {
    uint32_t a;
    asm("{ .reg .u64 t; cvta.to.shared.u64 t, %1; cvt.u32.u64 %0, t; }" : "=r"(a) : "l"(p));
    return a;
}

// ---------------- init ----------------
__global__ void zero_kernel() {
    int i = threadIdx.x;
    if (i < NE) g_cnt[i] = 0;
}

// ---------------- embedding gather (float4) ----------------
__global__ void embed_kernel(const int* __restrict__ tok, const float* __restrict__ emb,
                             float* __restrict__ x) {
    int t = blockIdx.x;
    const float4* src = (const float4*)(emb + (long)tok[t] * D);
    float4* dst = (float4*)(x + (long)t * D);
    for (int d = threadIdx.x; d < D/4; d += blockDim.x)
        dst[d] = src[d];
}

// ---------------- split builders ----------------
// A-pattern: [hi, lo, hi];  B-pattern: [whi, whi, wlo]
__global__ void xsplit_kernel(const float* __restrict__ x, __half* __restrict__ sp) {
    int t = blockIdx.x;
    const float* s = x + (long)t*D;
    __half* d0 = sp + (long)t*SPK;
    for (int c = threadIdx.x; c < D; c += 256) {
        float w = s[c];
        __half hi = __float2half_rn(w);
        __half lo = __float2half_rn(w - __half2float(hi));
        d0[c] = hi; d0[D + c] = lo; d0[2*D + c] = hi;
    }
}
__global__ void wsplit_kernel(const float* __restrict__ wq, const float* __restrict__ wk,
                              const float* __restrict__ wv, const float* __restrict__ wo) {
    int z = blockIdx.z;
    const float* src = (z == 0) ? wq : (z == 1) ? wk : (z == 2) ? wv : wo;
    __half* dst = (z < 3) ? (g_wsp + (long)z*D*SPK) : g_wosp;
    int row = blockIdx.x;
    const float* s = src + (long)row*D;
    __half* d0 = dst + (long)row*SPK;
    for (int c = threadIdx.x; c < D; c += 256) {
        float w = s[c];
        __half hi = __float2half_rn(w);
        __half lo = __float2half_rn(w - __half2float(hi));
        d0[c] = hi; d0[D + c] = hi; d0[2*D + c] = lo;
    }
}

// ---------------- RoPE tables ----------------
__global__ void rope_table_kernel() {
    int idx = blockIdx.x * blockDim.x + threadIdx.x;
    if (idx >= S*32) return;
    int j = idx & 31;
    int s = idx >> 5;
    double inv = pow(10000.0, -(double)(2*j) / (double)HD);
    double ang = (double)s * inv;
    g_cos[idx] = (float)cos(ang);
    g_sin[idx] = (float)sin(ang);
}

__global__ void rope_kernel(float* __restrict__ q, float* __restrict__ k) {
    int idx = blockIdx.x * blockDim.x + threadIdx.x;
    if (idx >= S*NH*(HD/2)) return;
    int j = idx & 31;
    int h = (idx >> 5) & 31;
    int s = idx >> 10;
    float c  = g_cos[s*32 + j];
    float sn = g_sin[s*32 + j];
    long base = (long)s*D + h*HD + 2*j;
    float q0 = q[base], q1 = q[base+1];
    q[base]   = q0*c - q1*sn;
    q[base+1] = q0*sn + q1*c;
    float k0 = k[base], k1 = k[base+1];
    k[base]   = k0*c - k1*sn;
    k[base+1] = k0*sn + k1*c;
}

// ---------------- attention: outputs split fp16 directly ----------------
#define ATTN_SMEM ((64*64 + 64*64 + 64*64 + 8*64) * 4)
__global__ void attn_kernel(const float* __restrict__ q, const float* __restrict__ k,
                            const float* __restrict__ v, __half* __restrict__ osp) {
    int h  = blockIdx.x;
    int ib = blockIdx.y;
    extern __shared__ float sm[];
    float* Qs  = sm;
    float* Ks2 = sm + 4096;
    float* Vs2 = sm + 8192;
    float* Ps  = sm + 12288;
    int tid = threadIdx.x;
    int w = tid >> 5, l = tid & 31;

    for (int idx = tid; idx < 64*64; idx += 256) {
        int r = idx >> 6, c = idx & 63;
        Qs[r*64 + c] = q[((long)(ib*BLKQ + r))*D + h*HD + c];
    }
    uint64_t num2[8];
    float den[8];
    #pragma unroll
    for (int r = 0; r < 8; r++) { num2[r] = 0ull; den[r] = 0.f; }

    for (int jb = 0; jb <= ib; jb++) {
        __syncthreads();
        for (int idx = tid; idx < 64*64; idx += 256) {
            int r = idx >> 6, c = idx & 63;
            float kv = k[((long)(jb*BLKQ + r))*D + h*HD + c];
            float vv = v[((long)(jb*BLKQ + r))*D + h*HD + c];
            Ks2[c*64 + (r & 31)*2 + (r >> 5)] = kv;
            Vs2[r*64 + (c & 31)*2 + (c >> 5)] = vv;
        }
        __syncthreads();
        for (int r = 0; r < 8; r++) {
            int qr = w*8 + r;
            uint64_t s2 = 0ull;
            #pragma unroll 8
            for (int d = 0; d < HD; d++) {
                uint64_t q2 = pack2(Qs[qr*64 + d]);
                uint64_t kp = *(const uint64_t*)&Ks2[d*64 + l*2];
                fma2(s2, q2, kp);
            }
            float s0, s1;
            unpack2(s2, s0, s1);
            s0 *= 0.125f; s1 *= 0.125f;
            if (jb == ib) {
                if (l      > qr) s0 = -INFINITY;
                if (l + 32 > qr) s1 = -INFINITY;
            }
            float m = fmaxf(s0, s1);
            #pragma unroll
            for (int off = 16; off; off >>= 1)
                m = fmaxf(m, __shfl_xor_sync(0xffffffffu, m, off));
            float p0 = expf(s0 - m), p1 = expf(s1 - m);
            float ds = p0 + p1;
            #pragma unroll
            for (int off = 16; off; off >>= 1)
                ds += __shfl_xor_sync(0xffffffffu, ds, off);
            den[r] += ds;
            Ps[w*64 + l] = p0; Ps[w*64 + l + 32] = p1;
            __syncwarp();
            #pragma unroll 8
            for (int kk = 0; kk < 64; kk++) {
                uint64_t pk2 = pack2(Ps[w*64 + kk]);
                uint64_t vp  = *(const uint64_t*)&Vs2[kk*64 + l*2];
                fma2(num2[r], pk2, vp);
            }
            __syncwarp();
        }
    }
    for (int r = 0; r < 8; r++) {
        int qr = w*8 + r;
        float dinv = 1.0f / (den[r] + 1e-6f);
        float n0, n1;
        unpack2(num2[r], n0, n1);
        long rb = ((long)(ib*BLKQ + qr))*SPK + h*HD;
        float v0 = n0 * dinv;
        __half h0 = __float2half_rn(v0);
        __half l0 = __float2half_rn(v0 - __half2float(h0));
        osp[rb + l]       = h0; osp[rb + D + l]   = l0; osp[rb + 2*D + l] = h0;
        float v1 = n1 * dinv;
        __half h1 = __float2half_rn(v1);
        __half l1 = __float2half_rn(v1 - __half2float(h1));
        osp[rb + l + 32]     = h1; osp[rb + D + l + 32] = l1; osp[rb + 2*D + l + 32] = h1;
    }
}

// ---------------- layernorm (also emits fp16 copy) ----------------
__global__ void ln_kernel(const float* __restrict__ x, const float* __restrict__ g,
                          const float* __restrict__ b, float* __restrict__ y,
                          __half* __restrict__ yh) {
    int t = blockIdx.x;
    __shared__ float red[256];
    const float* row = x + (long)t*D;
    float s = 0.f;
    for (int d = threadIdx.x; d < D; d += 256) s += row[d];
    red[threadIdx.x] = s; __syncthreads();
    for (int o = 128; o; o >>= 1) { if (threadIdx.x < o) red[threadIdx.x] += red[threadIdx.x+o]; __syncthreads(); }
    float mu = red[0] / (float)D;
    __syncthreads();
    float vs = 0.f;
    for (int d = threadIdx.x; d < D; d += 256) { float dd = row[d]-mu; vs = fmaf(dd, dd, vs); }
    red[threadIdx.x] = vs; __syncthreads();
    for (int o = 128; o; o >>= 1) { if (threadIdx.x < o) red[threadIdx.x] += red[threadIdx.x+o]; __syncthreads(); }
    float inv = 1.0f / sqrtf(red[0]/(float)D + 1e-5f);
    for (int d = threadIdx.x; d < D; d += 256) {
        float vvv = (row[d]-mu)*inv*g[d] + b[d];
        y[(long)t*D + d] = vvv;
        if (yh) yh[(long)t*D + d] = __float2half_rn(vvv);
    }
}

// --------- fused tail: gather expert outputs + residual + double LN -> fp16 ----------
__global__ void tail_kernel(const float* __restrict__ x2,
                            const float* __restrict__ g2, const float* __restrict__ b2,
                            const float* __restrict__ fg, const float* __restrict__ fb,
                            __half* __restrict__ yh) {
    int t = blockIdx.x;
    __shared__ float row[D];
    __shared__ float red[256];
    int tid = threadIdx.x;
    int  e1 = g_tok_e[t*2],   e2 = g_tok_e[t*2+1];
    int  s1 = g_tok_s[t*2],   s2 = g_tok_s[t*2+1];
    float w1 = g_tok_w[t*2],  w2 = g_tok_w[t*2+1];
    const float* y1 = g_t2 + ((long)e1*S + s1) * D;
    const float* y2 = g_t2 + ((long)e2*S + s2) * D;
    for (int d = tid; d < D; d += 256) {
        float a = w1 * y1[d];
        float b = w2 * y2[d];
        row[d] = (a + b) + x2[(long)t*D + d];
    }
    __syncthreads();
    float s = 0.f;
    for (int d = tid; d < D; d += 256) s += row[d];
    red[tid] = s; __syncthreads();
    for (int o = 128; o; o >>= 1) { if (tid < o) red[tid] += red[tid+o]; __syncthreads(); }
    float mu = red[0] / (float)D;
    __syncthreads();
    float vs = 0.f;
    for (int d = tid; d < D; d += 256) { float dd = row[d]-mu; vs = fmaf(dd, dd, vs); }
    red[tid] = vs; __syncthreads();
    for (int o = 128; o; o >>= 1) { if (tid < o) red[tid] += red[tid+o]; __syncthreads(); }
    float inv = 1.0f / sqrtf(red[0]/(float)D + 1e-5f);
    __syncthreads();
    for (int d = tid; d < D; d += 256)
        row[d] = (row[d]-mu)*inv*g2[d] + b2[d];
    __syncthreads();
    s = 0.f;
    for (int d = tid; d < D; d += 256) s += row[d];
    red[tid] = s; __syncthreads();
    for (int o = 128; o; o >>= 1) { if (tid < o) red[tid] += red[tid+o]; __syncthreads(); }
    mu = red[0] / (float)D;
    __syncthreads();
    vs = 0.f;
    for (int d = tid; d < D; d += 256) { float dd = row[d]-mu; vs = fmaf(dd, dd, vs); }
    red[tid] = vs; __syncthreads();
    for (int o = 128; o; o >>= 1) { if (tid < o) red[tid] += red[tid+o]; __syncthreads(); }
    inv = 1.0f / sqrtf(red[0]/(float)D + 1e-5f);
    for (int d = tid; d < D; d += 256)
        yh[(long)t*D + d] = __float2half_rn((row[d]-mu)*inv*fg[d] + fb[d]);
}

// ---------------- gate (+ per-token inverse routing map) ----------------
__global__ void gate_kernel(const float* __restrict__ x, const float* __restrict__ gw) {
    int t = blockIdx.x;
    int tid = threadIdx.x;  // 128
    __shared__ float red[4][128];
    const float* row = x + (long)t*D;
    float p[4] = {0.f,0.f,0.f,0.f};
    for (int d = tid; d < D; d += 128) {
        float xv = row[d];
        #pragma unroll
        for (int e = 0; e < 4; e++) p[e] = fmaf(xv, gw[e*D + d], p[e]);
    }
    #pragma unroll
    for (int e = 0; e < 4; e++) red[e][tid] = p[e];
    __syncthreads();
    for (int o = 64; o; o >>= 1) {
        if (tid < o) {
            red[0][tid] += red[0][tid+o];
            red[1][tid] += red[1][tid+o];
            red[2][tid] += red[2][tid+o];
            red[3][tid] += red[3][tid+o];
        }
        __syncthreads();
    }
    if (tid == 0) {
        float l[4];
        #pragma unroll
        for (int e = 0; e < 4; e++) l[e] = red[e][0];
        float mu = (l[0]+l[1]+l[2]+l[3]) * 0.25f;
        float var = 0.f;
        #pragma unroll
        for (int e = 0; e < 4; e++) { float d0 = l[e]-mu; var = fmaf(d0, d0, var); }
        g_var[t] = var / 3.0f;
        int i1 = 0;
        for (int e = 1; e < 4; e++) if (l[e] > l[i1]) i1 = e;
        int i2 = (i1 == 0) ? 1 : 0;
        for (int e = 0; e < 4; e++) if (e != i1 && l[e] > l[i2]) i2 = e;
        float m = fmaxf(fmaxf(l[0],l[1]), fmaxf(l[2],l[3]));
        float e1 = expf(l[i1]-m), e2 = expf(l[i2]-m);
        float w1 = e1/(e1+e2), w2 = e2/(e1+e2);
        int pos1 = atomicAdd(&g_cnt[i1], 1);
        g_list[i1*S + pos1] = t; g_wgt[i1*S + pos1] = w1;
        int pos2 = atomicAdd(&g_cnt[i2], 1);
        g_list[i2*S + pos2] = t; g_wgt[i2*S + pos2] = w2;
        g_tok_e[t*2] = i1;   g_tok_s[t*2] = pos1;   g_tok_w[t*2] = w1;
        g_tok_e[t*2+1] = i2; g_tok_s[t*2+1] = pos2; g_tok_w[t*2+1] = w2;
    }
}

// ---------------- aux ----------------
__global__ void aux_kernel(float* __restrict__ out, int out_size) {
    __shared__ float red[256];
    float s = 0.f;
    for (int i = threadIdx.x; i < S; i += 256) s += g_var[i];
    red[threadIdx.x] = s; __syncthreads();
    for (int o = 128; o; o >>= 1) { if (threadIdx.x < o) red[threadIdx.x] += red[threadIdx.x+o]; __syncthreads(); }
    if (threadIdx.x == 0) {
        long pos = (long)S * NV;
        if ((long)out_size > pos) out[pos] = red[0] / (float)S;
    }
}

// ---------------- silu-gate on valid routed rows: writes fp16 directly ----------------
__global__ void silu_kernel() {
    int row = blockIdx.x;
    int e = row >> 10;
    int slot = row & (S-1);
    if (slot >= g_cnt[e]) return;
    long base = (long)row * FF;
    const float4* t1p = (const float4*)(g_t1 + base);
    const float4* t2p = (const float4*)(g_t2 + base);
    uint2* oh = (uint2*)(g_t1h + base);
    for (int i = threadIdx.x; i < FF/4; i += 256) {
        float4 a = t1p[i], b = t2p[i];
        a.x = b.x * (a.x / (1.0f + expf(-a.x)));
        a.y = b.y * (a.y / (1.0f + expf(-a.y)));
        a.z = b.z * (a.z / (1.0f + expf(-a.z)));
        a.w = b.w * (a.w / (1.0f + expf(-a.w)));
        __half2 lo = __floats2half2_rn(a.x, a.y);
        __half2 hi = __floats2half2_rn(a.z, a.w);
        uint2 pk;
        pk.x = *(uint32_t*)&lo;
        pk.y = *(uint32_t*)&hi;
        oh[i] = pk;
    }
}

// ================= fp16 tensor-core GEMM: 128x128, 64x32 warp tile ===================
// m-tile on blockIdx.x (fastest) so co-resident CTAs share the B n-tile via L2.
constexpr int TBM = 128, TBN = 128, THK = 32;
constexpr int KPADH = 40;
constexpr size_t TSMEM = (size_t)2 * 2 * TBM * KPADH * sizeof(__half);  // 40960 B

__device__ __forceinline__ void ldsm4(uint32_t& r0, uint32_t& r1, uint32_t& r2, uint32_t& r3,
                                      uint32_t addr) {
    asm volatile("ldmatrix.sync.aligned.m8n8.x4.shared.b16 {%0,%1,%2,%3}, [%4];"
                 : "=r"(r0), "=r"(r1), "=r"(r2), "=r"(r3) : "r"(addr));
}

template<int EPI, bool GA, bool BHALF>
__device__ __forceinline__ void tgemm_body(
    const __half* __restrict__ A, const void* __restrict__ Bv, float* __restrict__ Cm,
    const float* __restrict__ resid,
    int Meff, int N, int K, const int* __restrict__ ridx, int m0, int n0)
{
    extern __shared__ __half hsh[];
    __half* Ah = hsh;                       // [2][TBM][KPADH]
    __half* Bh = hsh + 2*TBM*KPADH;
    uint32_t Abase = smem_u32(Ah);
    uint32_t Bbase = smem_u32(Bh);

    int tid = threadIdx.x, lane = tid & 31, wid = tid >> 5;
    int wm = (wid & 1) * 64;
    int wn = (wid >> 1) * 32;
    int lr = lane >> 2;
    int lc = lane & 3;

    int rr  = lane & 7, sub = lane >> 3;
    int a_row = rr + ((sub & 1) << 3);
    int a_kh  = (sub >> 1) << 3;
    int b_row = rr + ((sub >> 1) << 3);
    int b_kh  = (sub & 1) << 3;

    float acc[4][4][4];
    #pragma unroll
    for (int mt = 0; mt < 4; mt++)
        #pragma unroll
        for (int nt = 0; nt < 4; nt++)
            #pragma unroll
            for (int r = 0; r < 4; r++) acc[mt][nt][r] = 0.f;

    int arow_l = tid >> 1;
    int ach    = (tid & 1) * 16;
    const __half* ApH;
    {
        int arow = m0 + arow_l;
        bool av = arow < Meff;
        long grow = av ? (GA ? (long)ridx[arow] : (long)arow) : 0;
        ApH = av ? (A + grow*(long)K + ach) : nullptr;
    }
    const __half* BpH = nullptr;
    const float*  Bp[4];
    int kq = (tid & 7) * 4;
    int r0l = tid >> 3;
    if constexpr (BHALF) {
        const __half* Bg = (const __half*)Bv;
        int brow = n0 + arow_l;
        BpH = (brow < N) ? (Bg + (long)brow*K + ach) : nullptr;
    } else {
        const float* Bg = (const float*)Bv;
        #pragma unroll
        for (int i = 0; i < 4; i++) {
            int brow = n0 + r0l + 32*i;
            Bp[i] = (brow < N) ? (Bg + (long)brow*K + kq) : nullptr;
        }
    }

    uint4 av0, av1, bv0, bv1;
    float4 sb[4];
    const float4 z4 = make_float4(0.f,0.f,0.f,0.f);
    const uint4 zu4 = make_uint4(0,0,0,0);
    auto gload = [&](int kt) {
        av0 = ApH ? *(const uint4*)(ApH + (long)kt*THK)     : zu4;
        av1 = ApH ? *(const uint4*)(ApH + (long)kt*THK + 8) : zu4;
        if constexpr (BHALF) {
            bv0 = BpH ? *(const uint4*)(BpH + (long)kt*THK)     : zu4;
            bv1 = BpH ? *(const uint4*)(BpH + (long)kt*THK + 8) : zu4;
        } else {
            #pragma unroll
            for (int i = 0; i < 4; i++)
                sb[i] = Bp[i] ? *(const float4*)(Bp[i] + (long)kt*THK) : z4;
        }
    };
    auto sstore = [&](int buf) {
        uint4* pa = (uint4*)&Ah[((long)buf*TBM + arow_l)*KPADH + ach];
        pa[0] = av0; pa[1] = av1;
        if constexpr (BHALF) {
            uint4* pb = (uint4*)&Bh[((long)buf*TBM + arow_l)*KPADH + ach];
            pb[0] = bv0; pb[1] = bv1;
        } else {
            #pragma unroll
            for (int i = 0; i < 4; i++) {
                int ar = r0l + 32*i;
                __half2 b01 = __floats2half2_rn(sb[i].x, sb[i].y);
                __half2 b23 = __floats2half2_rn(sb[i].z, sb[i].w);
                __half2* pb = (__half2*)&Bh[((long)buf*TBM + ar)*KPADH + kq];
                pb[0] = b01; pb[1] = b23;
            }
        }
    };

    int ktiles = K / THK;
    gload(0);
    sstore(0);
    __syncthreads();

    for (int t = 0; t < ktiles; t++) {
        int buf = t & 1;
        bool more = (t + 1) < ktiles;
        if (more) gload(t + 1);

        uint32_t Abuf = Abase + (uint32_t)buf * TBM * KPADH * 2;
        uint32_t Bbuf = Bbase + (uint32_t)buf * TBM * KPADH * 2;

        #pragma unroll
        for (int ks = 0; ks < 2; ks++) {
            int kb = ks * 16;
            uint32_t af[4][4], bf[4][2];
            #pragma unroll
            for (int mt = 0; mt < 4; mt++) {
                uint32_t addr = Abuf + (uint32_t)((wm + mt*16 + a_row) * KPADH + kb + a_kh) * 2;
                ldsm4(af[mt][0], af[mt][1], af[mt][2], af[mt][3], addr);
            }
            #pragma unroll
            for (int p = 0; p < 2; p++) {
                uint32_t addr = Bbuf + (uint32_t)((wn + p*16 + b_row) * KPADH + kb + b_kh) * 2;
                ldsm4(bf[2*p][0], bf[2*p][1], bf[2*p+1][0], bf[2*p+1][1], addr);
            }
            #pragma unroll
            for (int mt = 0; mt < 4; mt++)
                #pragma unroll
                for (int nt = 0; nt < 4; nt++) {
                    asm volatile(
                        "mma.sync.aligned.m16n8k16.row.col.f32.f16.f16.f32 "
                        "{%0,%1,%2,%3}, {%4,%5,%6,%7}, {%8,%9}, {%0,%1,%2,%3};"
                        : "+f"(acc[mt][nt][0]), "+f"(acc[mt][nt][1]),
                          "+f"(acc[mt][nt][2]), "+f"(acc[mt][nt][3])
                        : "r"(af[mt][0]), "r"(af[mt][1]), "r"(af[mt][2]), "r"(af[mt][3]),
                          "r"(bf[nt][0]), "r"(bf[nt][1]));
                }
        }

        if (more) {
            sstore(buf ^ 1);
            __syncthreads();
        }
    }

    // ---------------- epilogue ----------------
    #pragma unroll
    for (int mt = 0; mt < 4; mt++) {
        int r0 = m0 + wm + mt*16 + lr;
        int r1 = r0 + 8;
        #pragma unroll
        for (int nt = 0; nt < 4; nt++) {
            int c0 = n0 + wn + nt*8 + (lc << 1);
            int c1 = c0 + 1;
            if (r0 < Meff) {
                if (c0 < N) {
                    float vv = acc[mt][nt][0];
                    if constexpr (EPI == 1) vv += resid[(long)r0*N + c0];
                    Cm[(long)r0*N + c0] = vv;
                }
                if (c1 < N) {
                    float vv = acc[mt][nt][1];
                    if constexpr (EPI == 1) vv += resid[(long)r0*N + c1];
                    Cm[(long)r0*N + c1] = vv;
                }
            }
            if (r1 < Meff) {
                if (c0 < N) {
                    float vv = acc[mt][nt][2];
                    if constexpr (EPI == 1) vv += resid[(long)r1*N + c0];
                    Cm[(long)r1*N + c0] = vv;
                }
                if (c1 < N) {
                    float vv = acc[mt][nt][3];
                    if constexpr (EPI == 1) vv += resid[(long)r1*N + c1];
                    Cm[(long)r1*N + c1] = vv;
                }
            }
        }
    }
}

// QKV: split-fp16 GEMM, z batches {q,k,v}, K' = 3D.  grid (S/TBM, D/TBN, 3)
__global__ void __launch_bounds__(256, 2)
qkv_gemm(float* __restrict__ q, float* __restrict__ k, float* __restrict__ v) {
    int z = blockIdx.z;
    float* Cm = (z == 0) ? q : (z == 1) ? k : v;
    const __half* Bm = g_wsp + (long)z*D*SPK;
    tgemm_body<0, false, true>(g_xsp, Bm, Cm, nullptr, S, D, SPK, nullptr,
                               blockIdx.x * TBM, blockIdx.y * TBN);
}

// WO: split-fp16 GEMM + residual.  grid (S/TBM, D/TBN)
__global__ void __launch_bounds__(256, 2)
wo_gemm(float* __restrict__ x1, const float* __restrict__ resid) {
    tgemm_body<1, false, true>(g_attsp, g_wosp, x1, resid, S, D, SPK, nullptr,
                               blockIdx.x * TBM, blockIdx.y * TBN);
}

// merged w1 + w3 MoE GEMM: grid (S/TBM, FF/TBN, 2*NE)
__global__ void __launch_bounds__(256, 2)
moe13_gemm(const float* __restrict__ w1, const float* __restrict__ w3,
           float* __restrict__ t1, float* __restrict__ t2) {
    int z = blockIdx.z;
    int e = z & (NE-1);
    int sel = z >> 2;
    int Meff = g_cnt[e];
    int m0 = blockIdx.x * TBM;
    if (m0 >= Meff) return;
    const float* Bm = (sel ? w3 : w1) + (long)e * FF * D;
    float*       Cm = (sel ? t2 : t1) + (long)e * S * FF;
    tgemm_body<0, true, false>(g_x2h, Bm, Cm, nullptr, Meff, FF, D, g_list + e*S,
                               m0, blockIdx.y * TBN);
}

// w2 GEMM: compact per-expert output rows.  grid (S/TBM, D/TBN, NE)
__global__ void __launch_bounds__(256, 2)
moe2_gemm(const float* __restrict__ w2, float* __restrict__ yout) {
    int e = blockIdx.z;
    int Meff = g_cnt[e];
    int m0 = blockIdx.x * TBM;
    if (m0 >= Meff) return;
    tgemm_body<0, false, false>(g_t1h + (long)e*S*FF, w2 + (long)e*D*FF, yout + (long)e*S*D,
                                nullptr, Meff, D, FF, nullptr, m0, blockIdx.y * TBN);
}

// LM head.  grid (S/TBM, ceil(NV/TBN))
__global__ void __launch_bounds__(256, 2)
head_gemm(const float* __restrict__ hw, float* __restrict__ out) {
    tgemm_body<0, false, false>(g_x5h, hw, out, nullptr, S, NV, D, nullptr,
                                blockIdx.x * TBM, blockIdx.y * TBN);
}

// ---------------- launcher ----------------
extern "C" void kernel_launch(void* const* d_in, const int* in_sizes, int n_in,
                              void* d_out, int out_size) {
    const int*   tokens = (const int*)  d_in[0];
    const float* emb    = (const float*)d_in[1];
    const float* wq     = (const float*)d_in[2];
    const float* wk     = (const float*)d_in[3];
    const float* wv     = (const float*)d_in[4];
    const float* wo     = (const float*)d_in[5];
    const float* ln1g   = (const float*)d_in[6];
    const float* ln1b   = (const float*)d_in[7];
    const float* gatew  = (const float*)d_in[8];
    const float* w1     = (const float*)d_in[9];
    const float* w2     = (const float*)d_in[10];
    const float* w3     = (const float*)d_in[11];
    const float* ln2g   = (const float*)d_in[12];
    const float* ln2b   = (const float*)d_in[13];
    const float* fing   = (const float*)d_in[14];
    const float* finb   = (const float*)d_in[15];
    const float* headw  = (const float*)d_in[16];
    float* out = (float*)d_out;

    float *x, *q, *k, *v, *x1, *x2, *t1, *t2;
    __half *x2h, *x5h, *xsp, *attsp;
    cudaGetSymbolAddress((void**)&x,   g_x);
    cudaGetSymbolAddress((void**)&q,   g_q);
    cudaGetSymbolAddress((void**)&k,   g_k);
    cudaGetSymbolAddress((void**)&v,   g_v);
    cudaGetSymbolAddress((void**)&x1,  g_x1);
    cudaGetSymbolAddress((void**)&x2,  g_x2);
    cudaGetSymbolAddress((void**)&t1,  g_t1);
    cudaGetSymbolAddress((void**)&t2,  g_t2);
    cudaGetSymbolAddress((void**)&x2h, g_x2h);
    cudaGetSymbolAddress((void**)&x5h, g_x5h);
    cudaGetSymbolAddress((void**)&xsp, g_xsp);
    cudaGetSymbolAddress((void**)&attsp, g_attsp);

    cudaFuncSetAttribute(attn_kernel, cudaFuncAttributeMaxDynamicSharedMemorySize, ATTN_SMEM);

    // 0. init + rope tables + weight splits
    zero_kernel<<<1, 32>>>();
    rope_table_kernel<<<(S*32 + 255)/256, 256>>>();
    wsplit_kernel<<<dim3(D, 1, 4), 256>>>(wq, wk, wv, wo);
    // 1. embedding + x split
    embed_kernel<<<S, 256>>>(tokens, emb, x);
    xsplit_kernel<<<S, 256>>>(x, xsp);
    // 2. QKV projections — split-fp16 tensor-core GEMM (m-tile fastest)
    qkv_gemm<<<dim3(S/TBM, D/TBN, 3), 256, TSMEM>>>(q, k, v);
    // 3. RoPE
    rope_kernel<<<(S*NH*(HD/2))/256, 256>>>(q, k);
    // 4. attention (emits split output)
    attn_kernel<<<dim3(NH, NB), 256, ATTN_SMEM>>>(q, k, v, attsp);
    // 5. output projection + residual — split-fp16
    wo_gemm<<<dim3(S/TBM, D/TBN, 1), 256, TSMEM>>>(x1, x);
    // 6. layernorm 1 (emits fp32 + fp16)
    ln_kernel<<<S, 256>>>(x1, ln1g, ln1b, x2, x2h);
    // 7. gating + routing + per-token variance
    gate_kernel<<<S, 128>>>(x2, gatew);
    aux_kernel<<<1, 256>>>(out, out_size);
    // 8. MoE expert GEMMs — fp16 tensor cores (m-tile fastest)
    moe13_gemm<<<dim3(S/TBM, FF/TBN, 2*NE), 256, TSMEM>>>(w1, w3, t1, t2);
    silu_kernel<<<NE*S, 256>>>();
    moe2_gemm<<<dim3(S/TBM, D/TBN, NE), 256, TSMEM>>>(w2, t2);   // t2 reused: [NE][S][D]
    // 9. fused gather + residual + double layernorm -> fp16 x5
    tail_kernel<<<S, 256>>>(x2, ln2g, ln2b, fing, finb, x5h);
    // 10. LM head — fp16 tensor cores (m-tile fastest)
    head_gemm<<<dim3(S/TBM, (NV + TBN - 1)/TBN, 1), 256, TSMEM>>>(headw, out);
}

// round 17
// speedup vs baseline: 1.6030x; 1.1972x over previous
#include <cuda_runtime.h>
#include <cuda_fp16.h>
#include <math.h>
#include <stdint.h>

#define S    1024
#define D    2048
#define NH   32
#define HD   64
#define FF   8192
#define NE   4
#define NV   50257
#define BLKQ 64
#define NB   16   // S / BLKQ
#define SPK  (3*D) // split-GEMM K' (hi*whi + lo*whi + hi*wlo)

// ---------------- scratch (static device globals; no runtime alloc) ----------------
__device__ float  g_x  [S*D];
__device__ float  g_q  [S*D];
__device__ float  g_k  [S*D];
__device__ float  g_v  [S*D];
__device__ float  g_x1 [S*D];
__device__ float  g_x2 [S*D];
__device__ float  g_t1 [(long)NE*S*FF];
__device__ float  g_t2 [(long)NE*S*FF];   // later reused as [NE][S][D] expert outputs
__device__ __half g_x2h[S*D];
__device__ __half g_t1h[(long)NE*S*FF];
__device__ __half g_x5h[S*D];
__device__ __half g_xsp  [(long)S*SPK];        // x split [hi,lo,hi]
__device__ __half g_attsp[(long)S*SPK];        // attention out split
__device__ __half g_wsp  [(long)3*D*SPK];      // wq/wk/wv split [whi,whi,wlo]
__device__ __half g_wosp [(long)D*SPK];        // wo split
__device__ int    g_cnt[NE];
__device__ int    g_list[NE*S];
__device__ float  g_wgt[NE*S];
__device__ int    g_tok_e[S*2];
__device__ int    g_tok_s[S*2];
__device__ float  g_tok_w[S*2];
__device__ float  g_var[S];
__device__ float  g_cos[S*32];
__device__ float  g_sin[S*32];

__device__ __forceinline__ uint32_t smem_u32(const void* p) {
    uint32_t a;
    asm("{ .reg .u64 t; cvta.to.shared.u64 t, %1; cvt.u32.u64 %0, t; }" : "=r"(a) : "l"(p));
    return a;
}
__device__ __forceinline__ void ldsm4(uint32_t& r0, uint32_t& r1, uint32_t& r2, uint32_t& r3,
                                      uint32_t addr) {
    asm volatile("ldmatrix.sync.aligned.m8n8.x4.shared.b16 {%0,%1,%2,%3}, [%4];"
                 : "=r"(r0), "=r"(r1), "=r"(r2), "=r"(r3) : "r"(addr));
}
#define MMA16816(ACC, AF, B0, B1) \
    asm volatile( \
        "mma.sync.aligned.m16n8k16.row.col.f32.f16.f16.f32 " \
        "{%0,%1,%2,%3}, {%4,%5,%6,%7}, {%8,%9}, {%0,%1,%2,%3};" \
        : "+f"((ACC)[0]), "+f"((ACC)[1]), "+f"((ACC)[2]), "+f"((ACC)[3]) \
        : "r"((AF)[0]), "r"((AF)[1]), "r"((AF)[2]), "r"((AF)[3]), "r"(B0), "r"(B1))

// ---------------- init ----------------
__global__ void zero_kernel() {
    int i = threadIdx.x;
    if (i < NE) g_cnt[i] = 0;
}

// ---------------- embedding gather (float4) ----------------
__global__ void embed_kernel(const int* __restrict__ tok, const float* __restrict__ emb,
                             float* __restrict__ x) {
    int t = blockIdx.x;
    const float4* src = (const float4*)(emb + (long)tok[t] * D);
    float4* dst = (float4*)(x + (long)t * D);
    for (int d = threadIdx.x; d < D/4; d += blockDim.x)
        dst[d] = src[d];
}

// ---------------- split builders ----------------
__global__ void xsplit_kernel(const float* __restrict__ x, __half* __restrict__ sp) {
    int t = blockIdx.x;
    const float* s = x + (long)t*D;
    __half* d0 = sp + (long)t*SPK;
    for (int c = threadIdx.x; c < D; c += 256) {
        float w = s[c];
        __half hi = __float2half_rn(w);
        __half lo = __float2half_rn(w - __half2float(hi));
        d0[c] = hi; d0[D + c] = lo; d0[2*D + c] = hi;
    }
}
__global__ void wsplit_kernel(const float* __restrict__ wq, const float* __restrict__ wk,
                              const float* __restrict__ wv, const float* __restrict__ wo) {
    int z = blockIdx.z;
    const float* src = (z == 0) ? wq : (z == 1) ? wk : (z == 2) ? wv : wo;
    __half* dst = (z < 3) ? (g_wsp + (long)z*D*SPK) : g_wosp;
    int row = blockIdx.x;
    const float* s = src + (long)row*D;
    __half* d0 = dst + (long)row*SPK;
    for (int c = threadIdx.x; c < D; c += 256) {
        float w = s[c];
        __half hi = __float2half_rn(w);
        __half lo = __float2half_rn(w - __half2float(hi));
        d0[c] = hi; d0[D + c] = hi; d0[2*D + c] = lo;
    }
}

// ---------------- RoPE tables ----------------
__global__ void rope_table_kernel() {
    int idx = blockIdx.x * blockDim.x + threadIdx.x;
    if (idx >= S*32) return;
    int j = idx & 31;
    int s = idx >> 5;
    double inv = pow(10000.0, -(double)(2*j) / (double)HD);
    double ang = (double)s * inv;
    g_cos[idx] = (float)cos(ang);
    g_sin[idx] = (float)sin(ang);
}

__global__ void rope_kernel(float* __restrict__ q, float* __restrict__ k) {
    int idx = blockIdx.x * blockDim.x + threadIdx.x;
    if (idx >= S*NH*(HD/2)) return;
    int j = idx & 31;
    int h = (idx >> 5) & 31;
    int s = idx >> 10;
    float c  = g_cos[s*32 + j];
    float sn = g_sin[s*32 + j];
    long base = (long)s*D + h*HD + 2*j;
    float q0 = q[base], q1 = q[base+1];
    q[base]   = q0*c - q1*sn;
    q[base+1] = q0*sn + q1*c;
    float k0 = k[base], k1 = k[base+1];
    k[base]   = k0*c - k1*sn;
    k[base+1] = k0*sn + k1*c;
}

// ---------------- tensor-core attention ----------------
// QK^T via 3-term split (K'=192, exact to ~1e-7); softmax fp32 in regs; PV fp16.
// 128 threads = 4 warps, each warp 16 query rows. Outputs split fp16.
constexpr int AQK = 192, AQP = 200;   // split K', padded row (400B, 16B aligned)
constexpr int AVP = 72;               // V^T row pad (144B)
constexpr int ATTN_SMEM2 = (64*AQP + 64*AQP + 64*AVP) * 2;   // 60416 B

__global__ void __launch_bounds__(128, 2)
attn_kernel(const float* __restrict__ q, const float* __restrict__ k,
            const float* __restrict__ v, __half* __restrict__ osp) {
    int h  = blockIdx.x;
    int ib = blockIdx.y;
    extern __shared__ __half ash[];
    __half* Qs = ash;                 // [64][AQP]  [qhi|qlo|qhi]
    __half* Ks = ash + 64*AQP;        // [64][AQP]  [khi|khi|klo]
    __half* Vs = ash + 2*64*AQP;      // [HD][AVP]  V^T fp16
    uint32_t Qbase = smem_u32(Qs);
    uint32_t Kbase = smem_u32(Ks);
    uint32_t Vbase = smem_u32(Vs);

    int tid = threadIdx.x, lane = tid & 31, wid = tid >> 5;
    int wq = wid * 16;
    int lr = lane >> 2, lc = lane & 3;
    int rr = lane & 7, sub = lane >> 3;
    int a_row = rr + ((sub & 1) << 3);
    int a_kh  = (sub >> 1) << 3;
    int b_row = rr + ((sub >> 1) << 3);
    int b_kh  = (sub & 1) << 3;

    // load Q tile, split
    for (int idx = tid; idx < 64*64; idx += 128) {
        int r = idx >> 6, c = idx & 63;
        float qv = q[((long)(ib*BLKQ + r))*D + h*HD + c];
        __half hi = __float2half_rn(qv);
        __half lo = __float2half_rn(qv - __half2float(hi));
        Qs[r*AQP + c] = hi; Qs[r*AQP + 64 + c] = lo; Qs[r*AQP + 128 + c] = hi;
    }

    float oa[8][4];
    float den0 = 0.f, den1 = 0.f;
    #pragma unroll
    for (int nt = 0; nt < 8; nt++)
        #pragma unroll
        for (int j = 0; j < 4; j++) oa[nt][j] = 0.f;

    for (int jb = 0; jb <= ib; jb++) {
        __syncthreads();
        // K tile split + V^T fp16
        for (int idx = tid; idx < 64*64; idx += 128) {
            int r = idx >> 6, c = idx & 63;
            float kv = k[((long)(jb*BLKQ + r))*D + h*HD + c];
            __half hi = __float2half_rn(kv);
            __half lo = __float2half_rn(kv - __half2float(hi));
            Ks[r*AQP + c] = hi; Ks[r*AQP + 64 + c] = hi; Ks[r*AQP + 128 + c] = lo;
            float vv = v[((long)(jb*BLKQ + r))*D + h*HD + c];
            Vs[c*AVP + r] = __float2half_rn(vv);
        }
        __syncthreads();

        // S = Q' @ K'^T over K'=192
        float sa[8][4];
        #pragma unroll
        for (int nt = 0; nt < 8; nt++)
            #pragma unroll
            for (int j = 0; j < 4; j++) sa[nt][j] = 0.f;

        for (int kt = 0; kt < AQK/16; kt++) {
            uint32_t af[4], bf[8][2];
            ldsm4(af[0], af[1], af[2], af[3],
                  Qbase + (uint32_t)((wq + a_row)*AQP + kt*16 + a_kh) * 2);
            #pragma unroll
            for (int p = 0; p < 4; p++)
                ldsm4(bf[2*p][0], bf[2*p][1], bf[2*p+1][0], bf[2*p+1][1],
                      Kbase + (uint32_t)((p*16 + b_row)*AQP + kt*16 + b_kh) * 2);
            #pragma unroll
            for (int nt = 0; nt < 8; nt++)
                MMA16816(sa[nt], af, bf[nt][0], bf[nt][1]);
        }

        // scale + causal mask
        int r0 = wq + lr, r1 = r0 + 8;
        #pragma unroll
        for (int nt = 0; nt < 8; nt++) {
            int c0 = nt*8 + 2*lc, c1 = c0 + 1;
            sa[nt][0] *= 0.125f; sa[nt][1] *= 0.125f;
            sa[nt][2] *= 0.125f; sa[nt][3] *= 0.125f;
            if (jb == ib) {
                if (c0 > r0) sa[nt][0] = -INFINITY;
                if (c1 > r0) sa[nt][1] = -INFINITY;
                if (c0 > r1) sa[nt][2] = -INFINITY;
                if (c1 > r1) sa[nt][3] = -INFINITY;
            }
        }
        // per-block row max (reduce over quad lanes)
        float m0 = -INFINITY, m1 = -INFINITY;
        #pragma unroll
        for (int nt = 0; nt < 8; nt++) {
            m0 = fmaxf(m0, fmaxf(sa[nt][0], sa[nt][1]));
            m1 = fmaxf(m1, fmaxf(sa[nt][2], sa[nt][3]));
        }
        #pragma unroll
        for (int off = 1; off <= 2; off <<= 1) {
            m0 = fmaxf(m0, __shfl_xor_sync(0xffffffffu, m0, off));
            m1 = fmaxf(m1, __shfl_xor_sync(0xffffffffu, m1, off));
        }
        // p = exp(s - m); den accumulation (fp32 p)
        float ds0 = 0.f, ds1 = 0.f;
        #pragma unroll
        for (int nt = 0; nt < 8; nt++) {
            sa[nt][0] = expf(sa[nt][0] - m0);
            sa[nt][1] = expf(sa[nt][1] - m0);
            sa[nt][2] = expf(sa[nt][2] - m1);
            sa[nt][3] = expf(sa[nt][3] - m1);
            ds0 += sa[nt][0] + sa[nt][1];
            ds1 += sa[nt][2] + sa[nt][3];
        }
        #pragma unroll
        for (int off = 1; off <= 2; off <<= 1) {
            ds0 += __shfl_xor_sync(0xffffffffu, ds0, off);
            ds1 += __shfl_xor_sync(0xffffffffu, ds1, off);
        }
        den0 += ds0; den1 += ds1;

        // O += P(fp16) @ V(fp16)
        #pragma unroll
        for (int kt = 0; kt < 4; kt++) {
            uint32_t af2[4];
            __half2 t0 = __floats2half2_rn(sa[2*kt][0],   sa[2*kt][1]);
            __half2 t1 = __floats2half2_rn(sa[2*kt][2],   sa[2*kt][3]);
            __half2 t2 = __floats2half2_rn(sa[2*kt+1][0], sa[2*kt+1][1]);
            __half2 t3 = __floats2half2_rn(sa[2*kt+1][2], sa[2*kt+1][3]);
            af2[0] = *(uint32_t*)&t0; af2[1] = *(uint32_t*)&t1;
            af2[2] = *(uint32_t*)&t2; af2[3] = *(uint32_t*)&t3;
            uint32_t bf[8][2];
            #pragma unroll
            for (int p = 0; p < 4; p++)
                ldsm4(bf[2*p][0], bf[2*p][1], bf[2*p+1][0], bf[2*p+1][1],
                      Vbase + (uint32_t)((p*16 + b_row)*AVP + kt*16 + b_kh) * 2);
            #pragma unroll
            for (int nt = 0; nt < 8; nt++)
                MMA16816(oa[nt], af2, bf[nt][0], bf[nt][1]);
        }
    }

    // write output split: O / (den + 1e-6)
    float d0 = 1.0f / (den0 + 1e-6f);
    float d1 = 1.0f / (den1 + 1e-6f);
    int r0 = ib*BLKQ + wq + lr, r1 = r0 + 8;
    long rb0 = (long)r0*SPK + h*HD;
    long rb1 = (long)r1*SPK + h*HD;
    #pragma unroll
    for (int nt = 0; nt < 8; nt++) {
        int c0 = nt*8 + 2*lc, c1 = c0 + 1;
        float v00 = oa[nt][0] * d0, v01 = oa[nt][1] * d0;
        float v10 = oa[nt][2] * d1, v11 = oa[nt][3] * d1;
        __half h00 = __float2half_rn(v00), l00 = __float2half_rn(v00 - __half2float(h00));
        __half h01 = __float2half_rn(v01), l01 = __float2half_rn(v01 - __half2float(h01));
        __half h10 = __float2half_rn(v10), l10 = __float2half_rn(v10 - __half2float(h10));
        __half h11 = __float2half_rn(v11), l11 = __float2half_rn(v11 - __half2float(h11));
        osp[rb0 + c0] = h00; osp[rb0 + D + c0] = l00; osp[rb0 + 2*D + c0] = h00;
        osp[rb0 + c1] = h01; osp[rb0 + D + c1] = l01; osp[rb0 + 2*D + c1] = h01;
        osp[rb1 + c0] = h10; osp[rb1 + D + c0] = l10; osp[rb1 + 2*D + c0] = h10;
        osp[rb1 + c1] = h11; osp[rb1 + D + c1] = l11; osp[rb1 + 2*D + c1] = h11;
    }
}

// ---------------- layernorm (also emits fp16 copy) ----------------
__global__ void ln_kernel(const float* __restrict__ x, const float* __restrict__ g,
                          const float* __restrict__ b, float* __restrict__ y,
                          __half* __restrict__ yh) {
    int t = blockIdx.x;
    __shared__ float red[256];
    const float* row = x + (long)t*D;
    float s = 0.f;
    for (int d = threadIdx.x; d < D; d += 256) s += row[d];
    red[threadIdx.x] = s; __syncthreads();
    for (int o = 128; o; o >>= 1) { if (threadIdx.x < o) red[threadIdx.x] += red[threadIdx.x+o]; __syncthreads(); }
    float mu = red[0] / (float)D;
    __syncthreads();
    float vs = 0.f;
    for (int d = threadIdx.x; d < D; d += 256) { float dd = row[d]-mu; vs = fmaf(dd, dd, vs); }
    red[threadIdx.x] = vs; __syncthreads();
    for (int o = 128; o; o >>= 1) { if (threadIdx.x < o) red[threadIdx.x] += red[threadIdx.x+o]; __syncthreads(); }
    float inv = 1.0f / sqrtf(red[0]/(float)D + 1e-5f);
    for (int d = threadIdx.x; d < D; d += 256) {
        float vvv = (row[d]-mu)*inv*g[d] + b[d];
        y[(long)t*D + d] = vvv;
        if (yh) yh[(long)t*D + d] = __float2half_rn(vvv);
    }
}

// --------- fused tail: gather expert outputs + residual + double LN -> fp16 ----------
__global__ void tail_kernel(const float* __restrict__ x2,
                            const float* __restrict__ g2, const float* __restrict__ b2,
                            const float* __restrict__ fg, const float* __restrict__ fb,
                            __half* __restrict__ yh) {
    int t = blockIdx.x;
    __shared__ float row[D];
    __shared__ float red[256];
    int tid = threadIdx.x;
    int  e1 = g_tok_e[t*2],   e2 = g_tok_e[t*2+1];
    int  s1 = g_tok_s[t*2],   s2 = g_tok_s[t*2+1];
    float w1 = g_tok_w[t*2],  w2 = g_tok_w[t*2+1];
    const float* y1 = g_t2 + ((long)e1*S + s1) * D;
    const float* y2 = g_t2 + ((long)e2*S + s2) * D;
    for (int d = tid; d < D; d += 256) {
        float a = w1 * y1[d];
        float b = w2 * y2[d];
        row[d] = (a + b) + x2[(long)t*D + d];
    }
    __syncthreads();
    float s = 0.f;
    for (int d = tid; d < D; d += 256) s += row[d];
    red[tid] = s; __syncthreads();
    for (int o = 128; o; o >>= 1) { if (tid < o) red[tid] += red[tid+o]; __syncthreads(); }
    float mu = red[0] / (float)D;
    __syncthreads();
    float vs = 0.f;
    for (int d = tid; d < D; d += 256) { float dd = row[d]-mu; vs = fmaf(dd, dd, vs); }
    red[tid] = vs; __syncthreads();
    for (int o = 128; o; o >>= 1) { if (tid < o) red[tid] += red[tid+o]; __syncthreads(); }
    float inv = 1.0f / sqrtf(red[0]/(float)D + 1e-5f);
    __syncthreads();
    for (int d = tid; d < D; d += 256)
        row[d] = (row[d]-mu)*inv*g2[d] + b2[d];
    __syncthreads();
    s = 0.f;
    for (int d = tid; d < D; d += 256) s += row[d];
    red[tid] = s; __syncthreads();
    for (int o = 128; o; o >>= 1) { if (tid < o) red[tid] += red[tid+o]; __syncthreads(); }
    mu = red[0] / (float)D;
    __syncthreads();
    vs = 0.f;
    for (int d = tid; d < D; d += 256) { float dd = row[d]-mu; vs = fmaf(dd, dd, vs); }
    red[tid] = vs; __syncthreads();
    for (int o = 128; o; o >>= 1) { if (tid < o) red[tid] += red[tid+o]; __syncthreads(); }
    inv = 1.0f / sqrtf(red[0]/(float)D + 1e-5f);
    for (int d = tid; d < D; d += 256)
        yh[(long)t*D + d] = __float2half_rn((row[d]-mu)*inv*fg[d] + fb[d]);
}

// ---------------- gate (+ per-token inverse routing map) ----------------
__global__ void gate_kernel(const float* __restrict__ x, const float* __restrict__ gw) {
    int t = blockIdx.x;
    int tid = threadIdx.x;  // 128
    __shared__ float red[4][128];
    const float* row = x + (long)t*D;
    float p[4] = {0.f,0.f,0.f,0.f};
    for (int d = tid; d < D; d += 128) {
        float xv = row[d];
        #pragma unroll
        for (int e = 0; e < 4; e++) p[e] = fmaf(xv, gw[e*D + d], p[e]);
    }
    #pragma unroll
    for (int e = 0; e < 4; e++) red[e][tid] = p[e];
    __syncthreads();
    for (int o = 64; o; o >>= 1) {
        if (tid < o) {
            red[0][tid] += red[0][tid+o];
            red[1][tid] += red[1][tid+o];
            red[2][tid] += red[2][tid+o];
            red[3][tid] += red[3][tid+o];
        }
        __syncthreads();
    }
    if (tid == 0) {
        float l[4];
        #pragma unroll
        for (int e = 0; e < 4; e++) l[e] = red[e][0];
        float mu = (l[0]+l[1]+l[2]+l[3]) * 0.25f;
        float var = 0.f;
        #pragma unroll
        for (int e = 0; e < 4; e++) { float d0 = l[e]-mu; var = fmaf(d0, d0, var); }
        g_var[t] = var / 3.0f;
        int i1 = 0;
        for (int e = 1; e < 4; e++) if (l[e] > l[i1]) i1 = e;
        int i2 = (i1 == 0) ? 1 : 0;
        for (int e = 0; e < 4; e++) if (e != i1 && l[e] > l[i2]) i2 = e;
        float m = fmaxf(fmaxf(l[0],l[1]), fmaxf(l[2],l[3]));
        float e1 = expf(l[i1]-m), e2 = expf(l[i2]-m);
        float w1 = e1/(e1+e2), w2 = e2/(e1+e2);
        int pos1 = atomicAdd(&g_cnt[i1], 1);
        g_list[i1*S + pos1] = t; g_wgt[i1*S + pos1] = w1;
        int pos2 = atomicAdd(&g_cnt[i2], 1);
        g_list[i2*S + pos2] = t; g_wgt[i2*S + pos2] = w2;
        g_tok_e[t*2] = i1;   g_tok_s[t*2] = pos1;   g_tok_w[t*2] = w1;
        g_tok_e[t*2+1] = i2; g_tok_s[t*2+1] = pos2; g_tok_w[t*2+1] = w2;
    }
}

// ---------------- aux ----------------
__global__ void aux_kernel(float* __restrict__ out, int out_size) {
    __shared__ float red[256];
    float s = 0.f;
    for (int i = threadIdx.x; i < S; i += 256) s += g_var[i];
    red[threadIdx.x] = s; __syncthreads();
    for (int o = 128; o; o >>= 1) { if (threadIdx.x < o) red[threadIdx.x] += red[threadIdx.x+o]; __syncthreads(); }
    if (threadIdx.x == 0) {
        long pos = (long)S * NV;
        if ((long)out_size > pos) out[pos] = red[0] / (float)S;
    }
}

// ---------------- silu-gate on valid routed rows: writes fp16 directly ----------------
__global__ void silu_kernel() {
    int row = blockIdx.x;
    int e = row >> 10;
    int slot = row & (S-1);
    if (slot >= g_cnt[e]) return;
    long base = (long)row * FF;
    const float4* t1p = (const float4*)(g_t1 + base);
    const float4* t2p = (const float4*)(g_t2 + base);
    uint2* oh = (uint2*)(g_t1h + base);
    for (int i = threadIdx.x; i < FF/4; i += 256) {
        float4 a = t1p[i], b = t2p[i];
        a.x = b.x * (a.x / (1.0f + expf(-a.x)));
        a.y = b.y * (a.y / (1.0f + expf(-a.y)));
        a.z = b.z * (a.z / (1.0f + expf(-a.z)));
        a.w = b.w * (a.w / (1.0f + expf(-a.w)));
        __half2 lo = __floats2half2_rn(a.x, a.y);
        __half2 hi = __floats2half2_rn(a.z, a.w);
        uint2 pk;
        pk.x = *(uint32_t*)&lo;
        pk.y = *(uint32_t*)&hi;
        oh[i] = pk;
    }
}

// ================= fp16 tensor-core GEMM: 128x128, 64x32 warp tile ===================
constexpr int TBM = 128, TBN = 128, THK = 32;
constexpr int KPADH = 40;
constexpr size_t TSMEM = (size_t)2 * 2 * TBM * KPADH * sizeof(__half);  // 40960 B

template<int EPI, bool GA, bool BHALF>
__device__ __forceinline__ void tgemm_body(
    const __half* __restrict__ A, const void* __restrict__ Bv, float* __restrict__ Cm,
    const float* __restrict__ resid,
    int Meff, int N, int K, const int* __restrict__ ridx, int m0, int n0)
{
    extern __shared__ __half hsh[];
    __half* Ah = hsh;
    __half* Bh = hsh + 2*TBM*KPADH;
    uint32_t Abase = smem_u32(Ah);
    uint32_t Bbase = smem_u32(Bh);

    int tid = threadIdx.x, lane = tid & 31, wid = tid >> 5;
    int wm = (wid & 1) * 64;
    int wn = (wid >> 1) * 32;
    int lr = lane >> 2;
    int lc = lane & 3;

    int rr  = lane & 7, sub = lane >> 3;
    int a_row = rr + ((sub & 1) << 3);
    int a_kh  = (sub >> 1) << 3;
    int b_row = rr + ((sub >> 1) << 3);
    int b_kh  = (sub & 1) << 3;

    float acc[4][4][4];
    #pragma unroll
    for (int mt = 0; mt < 4; mt++)
        #pragma unroll
        for (int nt = 0; nt < 4; nt++)
            #pragma unroll
            for (int r = 0; r < 4; r++) acc[mt][nt][r] = 0.f;

    int arow_l = tid >> 1;
    int ach    = (tid & 1) * 16;
    const __half* ApH;
    {
        int arow = m0 + arow_l;
        bool av = arow < Meff;
        long grow = av ? (GA ? (long)ridx[arow] : (long)arow) : 0;
        ApH = av ? (A + grow*(long)K + ach) : nullptr;
    }
    const __half* BpH = nullptr;
    const float*  Bp[4];
    int kq = (tid & 7) * 4;
    int r0l = tid >> 3;
    if constexpr (BHALF) {
        const __half* Bg = (const __half*)Bv;
        int brow = n0 + arow_l;
        BpH = (brow < N) ? (Bg + (long)brow*K + ach) : nullptr;
    } else {
        const float* Bg = (const float*)Bv;
        #pragma unroll
        for (int i = 0; i < 4; i++) {
            int brow = n0 + r0l + 32*i;
            Bp[i] = (brow < N) ? (Bg + (long)brow*K + kq) : nullptr;
        }
    }

    uint4 av0, av1, bv0, bv1;
    float4 sb[4];
    const float4 z4 = make_float4(0.f,0.f,0.f,0.f);
    const uint4 zu4 = make_uint4(0,0,0,0);
    auto gload = [&](int kt) {
        av0 = ApH ? *(const uint4*)(ApH + (long)kt*THK)     : zu4;
        av1 = ApH ? *(const uint4*)(ApH + (long)kt*THK + 8) : zu4;
        if constexpr (BHALF) {
            bv0 = BpH ? *(const uint4*)(BpH + (long)kt*THK)     : zu4;
            bv1 = BpH ? *(const uint4*)(BpH + (long)kt*THK + 8) : zu4;
        } else {
            #pragma unroll
            for (int i = 0; i < 4; i++)
                sb[i] = Bp[i] ? *(const float4*)(Bp[i] + (long)kt*THK) : z4;
        }
    };
    auto sstore = [&](int buf) {
        uint4* pa = (uint4*)&Ah[((long)buf*TBM + arow_l)*KPADH + ach];
        pa[0] = av0; pa[1] = av1;
        if constexpr (BHALF) {
            uint4* pb = (uint4*)&Bh[((long)buf*TBM + arow_l)*KPADH + ach];
            pb[0] = bv0; pb[1] = bv1;
        } else {
            #pragma unroll
            for (int i = 0; i < 4; i++) {
                int ar = r0l + 32*i;
                __half2 b01 = __floats2half2_rn(sb[i].x, sb[i].y);
                __half2 b23 = __floats2half2_rn(sb[i].z, sb[i].w);
                __half2* pb = (__half2*)&Bh[((long)buf*TBM + ar)*KPADH + kq];
                pb[0] = b01; pb[1] = b23;
            }
        }
    };

    int ktiles = K / THK;
    gload(0);
    sstore(0);
    __syncthreads();

    for (int t = 0; t < ktiles; t++) {
        int buf = t & 1;
        bool more = (t + 1) < ktiles;
        if (more) gload(t + 1);

        uint32_t Abuf = Abase + (uint32_t)buf * TBM * KPADH * 2;
        uint32_t Bbuf = Bbase + (uint32_t)buf * TBM * KPADH * 2;

        #pragma unroll
        for (int ks = 0; ks < 2; ks++) {
            int kb = ks * 16;
            uint32_t af[4][4], bf[4][2];
            #pragma unroll
            for (int mt = 0; mt < 4; mt++)
                ldsm4(af[mt][0], af[mt][1], af[mt][2], af[mt][3],
                      Abuf + (uint32_t)((wm + mt*16 + a_row) * KPADH + kb + a_kh) * 2);
            #pragma unroll
            for (int p = 0; p < 2; p++)
                ldsm4(bf[2*p][0], bf[2*p][1], bf[2*p+1][0], bf[2*p+1][1],
                      Bbuf + (uint32_t)((wn + p*16 + b_row) * KPADH + kb + b_kh) * 2);
            #pragma unroll
            for (int mt = 0; mt < 4; mt++)
                #pragma unroll
                for (int nt = 0; nt < 4; nt++)
                    MMA16816(acc[mt][nt], af[mt], bf[nt][0], bf[nt][1]);
        }

        if (more) {
            sstore(buf ^ 1);
            __syncthreads();
        }
    }

    #pragma unroll
    for (int mt = 0; mt < 4; mt++) {
        int r0 = m0 + wm + mt*16 + lr;
        int r1 = r0 + 8;
        #pragma unroll
        for (int nt = 0; nt < 4; nt++) {
            int c0 = n0 + wn + nt*8 + (lc << 1);
            int c1 = c0 + 1;
            if (r0 < Meff) {
                if (c0 < N) {
                    float vv = acc[mt][nt][0];
                    if constexpr (EPI == 1) vv += resid[(long)r0*N + c0];
                    Cm[(long)r0*N + c0] = vv;
                }
                if (c1 < N) {
                    float vv = acc[mt][nt][1];
                    if constexpr (EPI == 1) vv += resid[(long)r0*N + c1];
                    Cm[(long)r0*N + c1] = vv;
                }
            }
            if (r1 < Meff) {
                if (c0 < N) {
                    float vv = acc[mt][nt][2];
                    if constexpr (EPI == 1) vv += resid[(long)r1*N + c0];
                    Cm[(long)r1*N + c0] = vv;
                }
                if (c1 < N) {
                    float vv = acc[mt][nt][3];
                    if constexpr (EPI == 1) vv += resid[(long)r1*N + c1];
                    Cm[(long)r1*N + c1] = vv;
                }
            }
        }
    }
}

// QKV: split-fp16 GEMM, K' = 3D.  grid (S/TBM, D/TBN, 3)
__global__ void __launch_bounds__(256, 2)
qkv_gemm(float* __restrict__ q, float* __restrict__ k, float* __restrict__ v) {
    int z = blockIdx.z;
    float* Cm = (z == 0) ? q : (z == 1) ? k : v;
    const __half* Bm = g_wsp + (long)z*D*SPK;
    tgemm_body<0, false, true>(g_xsp, Bm, Cm, nullptr, S, D, SPK, nullptr,
                               blockIdx.x * TBM, blockIdx.y * TBN);
}

// WO: split-fp16 GEMM + residual.  grid (S/TBM, D/TBN)
__global__ void __launch_bounds__(256, 2)
wo_gemm(float* __restrict__ x1, const float* __restrict__ resid) {
    tgemm_body<1, false, true>(g_attsp, g_wosp, x1, resid, S, D, SPK, nullptr,
                               blockIdx.x * TBM, blockIdx.y * TBN);
}

// merged w1 + w3 MoE GEMM: grid (S/TBM, FF/TBN, 2*NE)
__global__ void __launch_bounds__(256, 2)
moe13_gemm(const float* __restrict__ w1, const float* __restrict__ w3,
           float* __restrict__ t1, float* __restrict__ t2) {
    int z = blockIdx.z;
    int e = z & (NE-1);
    int sel = z >> 2;
    int Meff = g_cnt[e];
    int m0 = blockIdx.x * TBM;
    if (m0 >= Meff) return;
    const float* Bm = (sel ? w3 : w1) + (long)e * FF * D;
    float*       Cm = (sel ? t2 : t1) + (long)e * S * FF;
    tgemm_body<0, true, false>(g_x2h, Bm, Cm, nullptr, Meff, FF, D, g_list + e*S,
                               m0, blockIdx.y * TBN);
}

// w2 GEMM: compact per-expert output rows.  grid (S/TBM, D/TBN, NE)
__global__ void __launch_bounds__(256, 2)
moe2_gemm(const float* __restrict__ w2, float* __restrict__ yout) {
    int e = blockIdx.z;
    int Meff = g_cnt[e];
    int m0 = blockIdx.x * TBM;
    if (m0 >= Meff) return;
    tgemm_body<0, false, false>(g_t1h + (long)e*S*FF, w2 + (long)e*D*FF, yout + (long)e*S*D,
                                nullptr, Meff, D, FF, nullptr, m0, blockIdx.y * TBN);
}

// LM head.  grid (S/TBM, ceil(NV/TBN))
__global__ void __launch_bounds__(256, 2)
head_gemm(const float* __restrict__ hw, float* __restrict__ out) {
    tgemm_body<0, false, false>(g_x5h, hw, out, nullptr, S, NV, D, nullptr,
                                blockIdx.x * TBM, blockIdx.y * TBN);
}

// ---------------- launcher ----------------
extern "C" void kernel_launch(void* const* d_in, const int* in_sizes, int n_in,
                              void* d_out, int out_size) {
    const int*   tokens = (const int*)  d_in[0];
    const float* emb    = (const float*)d_in[1];
    const float* wq     = (const float*)d_in[2];
    const float* wk     = (const float*)d_in[3];
    const float* wv     = (const float*)d_in[4];
    const float* wo     = (const float*)d_in[5];
    const float* ln1g   = (const float*)d_in[6];
    const float* ln1b   = (const float*)d_in[7];
    const float* gatew  = (const float*)d_in[8];
    const float* w1     = (const float*)d_in[9];
    const float* w2     = (const float*)d_in[10];
    const float* w3     = (const float*)d_in[11];
    const float* ln2g   = (const float*)d_in[12];
    const float* ln2b   = (const float*)d_in[13];
    const float* fing   = (const float*)d_in[14];
    const float* finb   = (const float*)d_in[15];
    const float* headw  = (const float*)d_in[16];
    float* out = (float*)d_out;

    float *x, *q, *k, *v, *x1, *x2, *t1, *t2;
    __half *x2h, *x5h, *xsp, *attsp;
    cudaGetSymbolAddress((void**)&x,   g_x);
    cudaGetSymbolAddress((void**)&q,   g_q);
    cudaGetSymbolAddress((void**)&k,   g_k);
    cudaGetSymbolAddress((void**)&v,   g_v);
    cudaGetSymbolAddress((void**)&x1,  g_x1);
    cudaGetSymbolAddress((void**)&x2,  g_x2);
    cudaGetSymbolAddress((void**)&t1,  g_t1);
    cudaGetSymbolAddress((void**)&t2,  g_t2);
    cudaGetSymbolAddress((void**)&x2h, g_x2h);
    cudaGetSymbolAddress((void**)&x5h, g_x5h);
    cudaGetSymbolAddress((void**)&xsp, g_xsp);
    cudaGetSymbolAddress((void**)&attsp, g_attsp);

    cudaFuncSetAttribute(attn_kernel, cudaFuncAttributeMaxDynamicSharedMemorySize, ATTN_SMEM2);

    // 0. init + rope tables + weight splits
    zero_kernel<<<1, 32>>>();
    rope_table_kernel<<<(S*32 + 255)/256, 256>>>();
    wsplit_kernel<<<dim3(D, 1, 4), 256>>>(wq, wk, wv, wo);
    // 1. embedding + x split
    embed_kernel<<<S, 256>>>(tokens, emb, x);
    xsplit_kernel<<<S, 256>>>(x, xsp);
    // 2. QKV projections — split-fp16 tensor-core GEMM
    qkv_gemm<<<dim3(S/TBM, D/TBN, 3), 256, TSMEM>>>(q, k, v);
    // 3. RoPE
    rope_kernel<<<(S*NH*(HD/2))/256, 256>>>(q, k);
    // 4. attention — tensor cores (split-QK exact, fp16 PV), emits split output
    attn_kernel<<<dim3(NH, NB), 128, ATTN_SMEM2>>>(q, k, v, attsp);
    // 5. output projection + residual — split-fp16
    wo_gemm<<<dim3(S/TBM, D/TBN, 1), 256, TSMEM>>>(x1, x);
    // 6. layernorm 1 (emits fp32 + fp16)
    ln_kernel<<<S, 256>>>(x1, ln1g, ln1b, x2, x2h);
    // 7. gating + routing + per-token variance
    gate_kernel<<<S, 128>>>(x2, gatew);
    aux_kernel<<<1, 256>>>(out, out_size);
    // 8. MoE expert GEMMs — fp16 tensor cores
    moe13_gemm<<<dim3(S/TBM, FF/TBN, 2*NE), 256, TSMEM>>>(w1, w3, t1, t2);
    silu_kernel<<<NE*S, 256>>>();
    moe2_gemm<<<dim3(S/TBM, D/TBN, NE), 256, TSMEM>>>(w2, t2);
    // 9. fused gather + residual + double layernorm -> fp16 x5
    tail_kernel<<<S, 256>>>(x2, ln2g, ln2b, fing, finb, x5h);
    // 10. LM head — fp16 tensor cores
    head_gemm<<<dim3(S/TBM, (NV + TBN - 1)/TBN, 1), 256, TSMEM>>>(headw, out);
}